// round 1
// baseline (speedup 1.0000x reference)
#include <cuda_runtime.h>
#include <math.h>

// ---------------- problem capacity constants ----------------
#define MAXN 50000
#define MAXE 800000
#define MAXEL (MAXE + MAXN)   // edges + self loops
#define FIN 128
#define HC1MAX 256

// ---------------- device scratch (no allocations allowed) ----------------
__device__ float g_xs[MAXN * FIN];          // standardized x
__device__ float g_h[MAXN * HC1MAX];        // GEMM output (h), reused per layer
__device__ float g_out1[MAXN * HC1MAX];     // layer1 output (post relu)
__device__ float g_asrc[MAXN * 4];
__device__ float g_adst[MAXN * 4];
__device__ float g_ebuf[MAXEL * 4];         // exp(leakyrelu(e)) per edge per head
__device__ int   g_counts[MAXN];
__device__ int   g_off[MAXN + 1];
__device__ int   g_cursor[MAXN];
__device__ int   g_col[MAXEL];
__device__ float g_part[256 * 260];         // column-stat partials
__device__ float g_mean[FIN];
__device__ float g_istd[FIN];
__device__ int   g_is64;

static inline int ceil_div(int a, int b) { return (a + b - 1) / b; }

// ---------------- edge index dtype detection ----------------
__global__ void detect_kernel(const unsigned int* p, int E) {
    __shared__ unsigned int acc;
    if (threadIdx.x == 0) acc = 0u;
    __syncthreads();
    int n = E < 1024 ? E : 1024;
    unsigned int v = 0;
    for (int i = threadIdx.x; i < n; i += blockDim.x) v |= p[2 * i + 1];
    atomicOr(&acc, v);
    __syncthreads();
    if (threadIdx.x == 0) g_is64 = (acc == 0u) ? 1 : 0;
}

__device__ __forceinline__ void get_edge(const void* ei, int E, int k, int& s, int& d) {
    if (g_is64) {
        const long long* p = (const long long*)ei;
        s = (int)p[k]; d = (int)p[E + k];
    } else {
        const int* p = (const int*)ei;
        s = p[k]; d = p[E + k];
    }
}

// ---------------- column stats (mean, std ddof=1) ----------------
__global__ void colstats1(const float* __restrict__ x, int N, int rowsPer) {
    int f = threadIdx.x;           // FIN threads
    int b = blockIdx.x;
    int r0 = b * rowsPer;
    int r1 = r0 + rowsPer; if (r1 > N) r1 = N;
    float s = 0.f, s2 = 0.f;
    for (int r = r0; r < r1; r++) {
        float v = x[(size_t)r * FIN + f];
        s += v; s2 += v * v;
    }
    g_part[b * 2 * FIN + f] = s;
    g_part[b * 2 * FIN + FIN + f] = s2;
}

__global__ void colstats2(int N, int nb) {
    int f = threadIdx.x;
    double s = 0.0, s2 = 0.0;
    for (int b = 0; b < nb; b++) {
        s  += (double)g_part[b * 2 * FIN + f];
        s2 += (double)g_part[b * 2 * FIN + FIN + f];
    }
    double mean = s / (double)N;
    double var = (s2 - s * s / (double)N) / (double)(N - 1);
    g_mean[f] = (float)mean;
    g_istd[f] = (float)(1.0 / sqrt(var));
}

__global__ void standardize_kernel(const float* __restrict__ x, int N) {
    int idx = blockIdx.x * blockDim.x + threadIdx.x;
    int total = N * (FIN / 4);
    if (idx >= total) return;
    int f4 = (idx & (FIN / 4 - 1)) * 4;
    float4 v = ((const float4*)x)[idx];
    v.x = (v.x - g_mean[f4 + 0]) * g_istd[f4 + 0];
    v.y = (v.y - g_mean[f4 + 1]) * g_istd[f4 + 1];
    v.z = (v.z - g_mean[f4 + 2]) * g_istd[f4 + 2];
    v.w = (v.w - g_mean[f4 + 3]) * g_istd[f4 + 3];
    ((float4*)g_xs)[idx] = v;
}

// ---------------- CSR build (by dst, self-loops included) ----------------
__global__ void csr_init(int N) {
    int i = blockIdx.x * blockDim.x + threadIdx.x;
    if (i < N) g_counts[i] = 1;   // self loop
}

__global__ void csr_count(const void* ei, int E) {
    int k = blockIdx.x * blockDim.x + threadIdx.x;
    if (k >= E) return;
    int s, d; get_edge(ei, E, k, s, d);
    atomicAdd(&g_counts[d], 1);
}

__global__ void csr_scan(int N) {
    __shared__ int sm[1024];
    int t = threadIdx.x;
    int chunk = (N + 1023) / 1024;
    int start = t * chunk;
    int end = start + chunk; if (end > N) end = N;
    int sum = 0;
    for (int i = start; i < end; i++) sum += g_counts[i];
    sm[t] = sum;
    __syncthreads();
    for (int o = 1; o < 1024; o <<= 1) {
        int v = (t >= o) ? sm[t - o] : 0;
        __syncthreads();
        sm[t] += v;
        __syncthreads();
    }
    int run = sm[t] - sum;   // exclusive
    for (int i = start; i < end; i++) {
        g_off[i] = run;
        g_cursor[i] = run;
        run += g_counts[i];
    }
    if (t == 1023) g_off[N] = sm[1023];
}

__global__ void csr_scatter(const void* ei, int E, int N) {
    int k = blockIdx.x * blockDim.x + threadIdx.x;
    if (k >= E + N) return;
    int s, d;
    if (k < E) get_edge(ei, E, k, s, d);
    else { s = k - E; d = s; }
    int pos = atomicAdd(&g_cursor[d], 1);
    g_col[pos] = s;
}

// ---------------- fp32 tiled GEMM: C[N,M] = A[N,K] @ B[K,M] ----------------
// BM=64, BN=64, BK=16, 256 threads, 4x4 micro-tile. A selected from globals.
__global__ void gemm_kernel(int asel, const float* __restrict__ B, int N, int K, int M) {
    const float* __restrict__ A = asel ? g_out1 : g_xs;
    float* __restrict__ C = g_h;
    __shared__ float As[16][68];   // transposed A tile, padded
    __shared__ float Bs[16][64];
    int t = threadIdx.x;
    int tx = t & 15, ty = t >> 4;
    int row0 = blockIdx.x * 64;
    int col0 = blockIdx.y * 64;

    int aRow = t >> 2;            // 0..63
    int aK4 = (t & 3) * 4;        // 0,4,8,12
    int bK = t >> 4;              // 0..15
    int bC4 = (t & 15) * 4;       // 0..60

    float acc[4][4];
#pragma unroll
    for (int i = 0; i < 4; i++)
#pragma unroll
        for (int j = 0; j < 4; j++) acc[i][j] = 0.f;

    for (int kk = 0; kk < K; kk += 16) {
        float4 av = make_float4(0.f, 0.f, 0.f, 0.f);
        int gr = row0 + aRow;
        if (gr < N) av = *(const float4*)(A + (size_t)gr * K + kk + aK4);
        As[aK4 + 0][aRow] = av.x;
        As[aK4 + 1][aRow] = av.y;
        As[aK4 + 2][aRow] = av.z;
        As[aK4 + 3][aRow] = av.w;

        float4 bv = make_float4(0.f, 0.f, 0.f, 0.f);
        int gc = col0 + bC4;
        if (gc < M) bv = *(const float4*)(B + (size_t)(kk + bK) * M + gc);
        *(float4*)&Bs[bK][bC4] = bv;

        __syncthreads();
#pragma unroll
        for (int k = 0; k < 16; k++) {
            float4 a4 = *(float4*)&As[k][ty * 4];
            float4 b4 = *(float4*)&Bs[k][tx * 4];
            float a[4] = {a4.x, a4.y, a4.z, a4.w};
            float b[4] = {b4.x, b4.y, b4.z, b4.w};
#pragma unroll
            for (int i = 0; i < 4; i++)
#pragma unroll
                for (int j = 0; j < 4; j++) acc[i][j] += a[i] * b[j];
        }
        __syncthreads();
    }

    int gc = col0 + tx * 4;
    if (gc < M) {
#pragma unroll
        for (int i = 0; i < 4; i++) {
            int gr = row0 + ty * 4 + i;
            if (gr < N) {
                float4 v = make_float4(acc[i][0], acc[i][1], acc[i][2], acc[i][3]);
                *(float4*)(C + (size_t)gr * M + gc) = v;
            }
        }
    }
}

// ---------------- attention coefficients: a_src/a_dst [N,H] ----------------
__global__ void att_kernel(const float* __restrict__ att_s, const float* __restrict__ att_d,
                           int N, int C) {
    int warp = (blockIdx.x * blockDim.x + threadIdx.x) >> 5;
    int lane = threadIdx.x & 31;
    int total = N * 4;
    if (warp >= total) return;
    int n = warp >> 2, hh = warp & 3;
    const float* hp = g_h + (size_t)n * 4 * C + hh * C;
    float s1 = 0.f, s2 = 0.f;
    for (int c = lane; c < C; c += 32) {
        float v = hp[c];
        s1 += v * att_s[hh * C + c];
        s2 += v * att_d[hh * C + c];
    }
#pragma unroll
    for (int o = 16; o; o >>= 1) {
        s1 += __shfl_xor_sync(0xffffffffu, s1, o);
        s2 += __shfl_xor_sync(0xffffffffu, s2, o);
    }
    if (lane == 0) {
        g_asrc[n * 4 + hh] = s1;
        g_adst[n * 4 + hh] = s2;
    }
}

// ---------------- aggregation: warp per dst, CSR, register accumulation ----
__global__ void agg_kernel(const float* __restrict__ bias, float* __restrict__ out_ext,
                           int use_ext, int N, int HC, int C, int do_relu) {
    float* out = use_ext ? out_ext : g_out1;
    int warp = (blockIdx.x * blockDim.x + threadIdx.x) >> 5;
    int lane = threadIdx.x & 31;
    if (warp >= N) return;
    int d = warp;
    int beg = g_off[d], end = g_off[d + 1];
    float4 ad = *(const float4*)(g_adst + d * 4);

    // pass 1: exp(leakyrelu) per edge per head, denominators
    float den0 = 0.f, den1 = 0.f, den2 = 0.f, den3 = 0.f;
    for (int i = beg + lane; i < end; i += 32) {
        int s = g_col[i];
        float4 as = *(const float4*)(g_asrc + s * 4);
        float e0 = as.x + ad.x; e0 = e0 > 0.f ? e0 : 0.2f * e0; e0 = __expf(e0);
        float e1 = as.y + ad.y; e1 = e1 > 0.f ? e1 : 0.2f * e1; e1 = __expf(e1);
        float e2 = as.z + ad.z; e2 = e2 > 0.f ? e2 : 0.2f * e2; e2 = __expf(e2);
        float e3 = as.w + ad.w; e3 = e3 > 0.f ? e3 : 0.2f * e3; e3 = __expf(e3);
        *(float4*)(g_ebuf + (size_t)i * 4) = make_float4(e0, e1, e2, e3);
        den0 += e0; den1 += e1; den2 += e2; den3 += e3;
    }
#pragma unroll
    for (int o = 16; o; o >>= 1) {
        den0 += __shfl_xor_sync(0xffffffffu, den0, o);
        den1 += __shfl_xor_sync(0xffffffffu, den1, o);
        den2 += __shfl_xor_sync(0xffffffffu, den2, o);
        den3 += __shfl_xor_sync(0xffffffffu, den3, o);
    }
    float r0 = 1.f / den0, r1 = 1.f / den1, r2 = 1.f / den2, r3 = 1.f / den3;

    // per-lane feature mapping (HC >= 128 guaranteed: 256 or 160)
    int j0 = lane * 4;
    int h0 = j0 / C;
    int j1 = 128 + lane * 4;
    bool has1 = (j1 < HC);
    int h1 = has1 ? (j1 / C) : 0;

    float4 acc0 = make_float4(0.f, 0.f, 0.f, 0.f);
    float4 acc1 = make_float4(0.f, 0.f, 0.f, 0.f);

    for (int i = beg; i < end; i++) {
        int s = g_col[i];                                  // uniform across warp
        float4 e = *(const float4*)(g_ebuf + (size_t)i * 4);
        float a0 = e.x * r0, a1 = e.y * r1, a2 = e.z * r2, a3 = e.w * r3;
        float aa = h0 == 0 ? a0 : (h0 == 1 ? a1 : (h0 == 2 ? a2 : a3));
        const float* hp = g_h + (size_t)s * HC;
        float4 v0 = *(const float4*)(hp + j0);
        acc0.x += aa * v0.x; acc0.y += aa * v0.y;
        acc0.z += aa * v0.z; acc0.w += aa * v0.w;
        if (has1) {
            float ab = h1 == 0 ? a0 : (h1 == 1 ? a1 : (h1 == 2 ? a2 : a3));
            float4 v1 = *(const float4*)(hp + j1);
            acc1.x += ab * v1.x; acc1.y += ab * v1.y;
            acc1.z += ab * v1.z; acc1.w += ab * v1.w;
        }
    }

    float4 b0 = *(const float4*)(bias + j0);
    acc0.x += b0.x; acc0.y += b0.y; acc0.z += b0.z; acc0.w += b0.w;
    if (do_relu) {
        acc0.x = fmaxf(acc0.x, 0.f); acc0.y = fmaxf(acc0.y, 0.f);
        acc0.z = fmaxf(acc0.z, 0.f); acc0.w = fmaxf(acc0.w, 0.f);
    }
    *(float4*)(out + (size_t)d * HC + j0) = acc0;
    if (has1) {
        float4 b1 = *(const float4*)(bias + j1);
        acc1.x += b1.x; acc1.y += b1.y; acc1.z += b1.z; acc1.w += b1.w;
        if (do_relu) {
            acc1.x = fmaxf(acc1.x, 0.f); acc1.y = fmaxf(acc1.y, 0.f);
            acc1.z = fmaxf(acc1.z, 0.f); acc1.w = fmaxf(acc1.w, 0.f);
        }
        *(float4*)(out + (size_t)d * HC + j1) = acc1;
    }
}

// ---------------- launch ----------------
extern "C" void kernel_launch(void* const* d_in, const int* in_sizes, int n_in,
                              void* d_out, int out_size) {
    const float* x   = (const float*)d_in[0];
    const void*  ei  = d_in[1];
    const float* W1  = (const float*)d_in[2];
    const float* as1 = (const float*)d_in[3];
    const float* ad1 = (const float*)d_in[4];
    const float* b1  = (const float*)d_in[5];
    const float* W2  = (const float*)d_in[6];
    const float* as2 = (const float*)d_in[7];
    const float* ad2 = (const float*)d_in[8];
    const float* b2  = (const float*)d_in[9];

    int E = in_sizes[1] / 2;
    int HC1 = in_sizes[5];          // b1 length (256)
    int HC2 = in_sizes[9];          // b2 length (160)
    int F = in_sizes[2] / HC1;      // 128
    int N = in_sizes[0] / F;        // 50000
    int C1 = HC1 / 4;
    int C2 = HC2 / 4;

    // dtype detection for edge_index
    detect_kernel<<<1, 256>>>((const unsigned int*)ei, E);

    // column stats + standardize
    int nb = 200;
    int rowsPer = ceil_div(N, nb);
    colstats1<<<nb, FIN>>>(x, N, rowsPer);
    colstats2<<<1, FIN>>>(N, nb);
    standardize_kernel<<<ceil_div(N * (F / 4), 256), 256>>>(x, N);

    // CSR build (shared by both layers)
    csr_init<<<ceil_div(N, 256), 256>>>(N);
    csr_count<<<ceil_div(E, 256), 256>>>(ei, E);
    csr_scan<<<1, 1024>>>(N);
    csr_scatter<<<ceil_div(E + N, 256), 256>>>(ei, E, N);

    // ---- layer 1 ----
    {
        dim3 grid(ceil_div(N, 64), ceil_div(HC1, 64));
        gemm_kernel<<<grid, 256>>>(0, W1, N, F, HC1);
    }
    att_kernel<<<ceil_div(N * 4, 8), 256>>>(as1, ad1, N, C1);
    agg_kernel<<<ceil_div(N, 8), 256>>>(b1, nullptr, 0, N, HC1, C1, 1);

    // ---- layer 2 ----
    {
        dim3 grid(ceil_div(N, 64), ceil_div(HC2, 64));
        gemm_kernel<<<grid, 256>>>(1, W2, N, HC1, HC2);
    }
    att_kernel<<<ceil_div(N * 4, 8), 256>>>(as2, ad2, N, C2);
    agg_kernel<<<ceil_div(N, 8), 256>>>(b2, (float*)d_out, 1, N, HC2, C2, 0);
}

// round 4
// speedup vs baseline: 1.1768x; 1.1768x over previous
#include <cuda_runtime.h>
#include <math.h>

// ---------------- problem capacity constants ----------------
#define MAXN 50000
#define MAXE 800000
#define MAXEL (MAXE + MAXN)   // edges + self loops
#define FIN 128
#define HC1MAX 256

// ---------------- device scratch (no allocations allowed) ----------------
__device__ float g_xs[MAXN * FIN];          // standardized x
__device__ float g_h[MAXN * HC1MAX];        // GEMM output (h), reused per layer
__device__ float g_out1[MAXN * HC1MAX];     // layer1 output (post relu)
__device__ float g_asrc[MAXN * 4];
__device__ float g_adst[MAXN * 4];
__device__ float g_ebuf[MAXEL * 4];         // exp(leakyrelu(e)) per edge per head
__device__ int   g_counts[MAXN];
__device__ int   g_off[MAXN + 1];
__device__ int   g_cursor[MAXN];
__device__ int   g_col[MAXEL];
__device__ float g_part[256 * 260];         // column-stat partials
__device__ float g_mean[FIN];
__device__ float g_istd[FIN];
__device__ int   g_is64;

static inline int ceil_div(int a, int b) { return (a + b - 1) / b; }

// ---------------- edge index dtype detection ----------------
__global__ void detect_kernel(const unsigned int* p, int E) {
    __shared__ unsigned int acc;
    if (threadIdx.x == 0) acc = 0u;
    __syncthreads();
    int n = E < 1024 ? E : 1024;
    unsigned int v = 0;
    for (int i = threadIdx.x; i < n; i += blockDim.x) v |= p[2 * i + 1];
    atomicOr(&acc, v);
    __syncthreads();
    if (threadIdx.x == 0) g_is64 = (acc == 0u) ? 1 : 0;
}

__device__ __forceinline__ void get_edge(const void* ei, int E, int k, int& s, int& d) {
    if (g_is64) {
        const long long* p = (const long long*)ei;
        s = (int)p[k]; d = (int)p[E + k];
    } else {
        const int* p = (const int*)ei;
        s = p[k]; d = p[E + k];
    }
}

// ---------------- column stats (mean, std ddof=1) ----------------
__global__ void colstats1(const float* __restrict__ x, int N, int rowsPer) {
    int f = threadIdx.x;           // FIN threads
    int b = blockIdx.x;
    int r0 = b * rowsPer;
    int r1 = r0 + rowsPer; if (r1 > N) r1 = N;
    float s = 0.f, s2 = 0.f;
    for (int r = r0; r < r1; r++) {
        float v = x[(size_t)r * FIN + f];
        s += v; s2 += v * v;
    }
    g_part[b * 2 * FIN + f] = s;
    g_part[b * 2 * FIN + FIN + f] = s2;
}

__global__ void colstats2(int N, int nb) {
    int f = threadIdx.x;
    double s = 0.0, s2 = 0.0;
    for (int b = 0; b < nb; b++) {
        s  += (double)g_part[b * 2 * FIN + f];
        s2 += (double)g_part[b * 2 * FIN + FIN + f];
    }
    double mean = s / (double)N;
    double var = (s2 - s * s / (double)N) / (double)(N - 1);
    g_mean[f] = (float)mean;
    g_istd[f] = (float)(1.0 / sqrt(var));
}

__global__ void standardize_kernel(const float* __restrict__ x, int N) {
    int idx = blockIdx.x * blockDim.x + threadIdx.x;
    int total = N * (FIN / 4);
    if (idx >= total) return;
    int f4 = (idx & (FIN / 4 - 1)) * 4;
    float4 v = ((const float4*)x)[idx];
    v.x = (v.x - g_mean[f4 + 0]) * g_istd[f4 + 0];
    v.y = (v.y - g_mean[f4 + 1]) * g_istd[f4 + 1];
    v.z = (v.z - g_mean[f4 + 2]) * g_istd[f4 + 2];
    v.w = (v.w - g_mean[f4 + 3]) * g_istd[f4 + 3];
    ((float4*)g_xs)[idx] = v;
}

// ---------------- CSR build (by dst, self-loops included) ----------------
__global__ void csr_init(int N) {
    int i = blockIdx.x * blockDim.x + threadIdx.x;
    if (i < N) g_counts[i] = 1;   // self loop
}

__global__ void csr_count(const void* ei, int E) {
    int k = blockIdx.x * blockDim.x + threadIdx.x;
    if (k >= E) return;
    int s, d; get_edge(ei, E, k, s, d);
    atomicAdd(&g_counts[d], 1);
}

__global__ void csr_scan(int N) {
    __shared__ int sm[1024];
    int t = threadIdx.x;
    int chunk = (N + 1023) / 1024;
    int start = t * chunk;
    int end = start + chunk; if (end > N) end = N;
    int sum = 0;
    for (int i = start; i < end; i++) sum += g_counts[i];
    sm[t] = sum;
    __syncthreads();
    for (int o = 1; o < 1024; o <<= 1) {
        int v = (t >= o) ? sm[t - o] : 0;
        __syncthreads();
        sm[t] += v;
        __syncthreads();
    }
    int run = sm[t] - sum;   // exclusive
    for (int i = start; i < end; i++) {
        g_off[i] = run;
        g_cursor[i] = run;
        run += g_counts[i];
    }
    if (t == 1023) g_off[N] = sm[1023];
}

__global__ void csr_scatter(const void* ei, int E, int N) {
    int k = blockIdx.x * blockDim.x + threadIdx.x;
    if (k >= E + N) return;
    int s, d;
    if (k < E) get_edge(ei, E, k, s, d);
    else { s = k - E; d = s; }
    int pos = atomicAdd(&g_cursor[d], 1);
    g_col[pos] = s;
}

// ---------------- tf32 tensor-core GEMM ----------------
// C[N,M] = A[N,K] @ B[K,M].  BM=128, BN=64, BK=32, 256 threads (8 warps, 4x2).
// Warp tile 32x32 = 2x4 m16n8k8 mma. fp32->tf32 rounded in gmem->smem path.

__device__ __forceinline__ unsigned int f2tf32(float f) {
    unsigned int r;
    asm("cvt.rna.tf32.f32 %0, %1;" : "=r"(r) : "f"(f));
    return r;
}

__device__ __forceinline__ void mma_tf32(float* c, const unsigned int* a, const unsigned int* b) {
    asm volatile(
        "mma.sync.aligned.m16n8k8.row.col.f32.tf32.tf32.f32 "
        "{%0,%1,%2,%3}, {%4,%5,%6,%7}, {%8,%9}, {%0,%1,%2,%3};\n"
        : "+f"(c[0]), "+f"(c[1]), "+f"(c[2]), "+f"(c[3])
        : "r"(a[0]), "r"(a[1]), "r"(a[2]), "r"(a[3]), "r"(b[0]), "r"(b[1]));
}

__global__ __launch_bounds__(256, 2)
void gemm_tf32_kernel(int asel, const float* __restrict__ B, int N, int K, int M) {
    const float* __restrict__ A = asel ? g_out1 : g_xs;
    float* __restrict__ C = g_h;

    // k-major smem; pads chosen so fragment LDS banks = (tig*8+groupID)%32 (conflict-free)
    __shared__ unsigned int As[32][136];   // [k][m], m-pad 128->136
    __shared__ unsigned int Bs[32][72];    // [k][n], n-pad 64->72

    int t = threadIdx.x;
    int lane = t & 31;
    int warp = t >> 5;
    int groupID = lane >> 2;
    int tig = lane & 3;
    int warp_m = warp >> 1;   // 0..3
    int warp_n = warp & 1;    // 0..1

    int row0 = blockIdx.x * 128;
    int col0 = blockIdx.y * 64;

    // global-load assignment
    int aRow = t >> 1;          // 0..127
    int aC0  = (t & 1) * 16;    // 0 or 16
    int bRow = t >> 3;          // 0..31
    int bC0  = (t & 7) * 8;     // 0..56

    float acc[2][4][4];
#pragma unroll
    for (int i = 0; i < 2; i++)
#pragma unroll
        for (int j = 0; j < 4; j++)
#pragma unroll
            for (int c = 0; c < 4; c++) acc[i][j][c] = 0.f;

    int T = K >> 5;

    float aSt[16];
    float bSt[8];

    int gRowA = row0 + aRow;
    bool aOK = gRowA < N;
    int gColB = col0 + bC0;
    bool bOK = gColB < M;           // M multiple of 8 -> whole 8-chunk in/out

    // ---- stage tile 0 ----
    {
        const float* ap = A + (size_t)gRowA * K + aC0;
#pragma unroll
        for (int q = 0; q < 4; q++) {
            float4 v = aOK ? *(const float4*)(ap + q * 4) : make_float4(0.f, 0.f, 0.f, 0.f);
            aSt[q * 4 + 0] = v.x; aSt[q * 4 + 1] = v.y;
            aSt[q * 4 + 2] = v.z; aSt[q * 4 + 3] = v.w;
        }
        const float* bp = B + (size_t)bRow * M + gColB;
#pragma unroll
        for (int q = 0; q < 2; q++) {
            float4 v = bOK ? *(const float4*)(bp + q * 4) : make_float4(0.f, 0.f, 0.f, 0.f);
            bSt[q * 4 + 0] = v.x; bSt[q * 4 + 1] = v.y;
            bSt[q * 4 + 2] = v.z; bSt[q * 4 + 3] = v.w;
        }
    }
#pragma unroll
    for (int i = 0; i < 16; i++) As[aC0 + i][aRow] = f2tf32(aSt[i]);
#pragma unroll
    for (int i = 0; i < 8; i++)  Bs[bRow][bC0 + i] = f2tf32(bSt[i]);
    __syncthreads();

    for (int tt = 0; tt < T; tt++) {
        // prefetch next tile into registers
        if (tt + 1 < T) {
            const float* ap = A + (size_t)gRowA * K + (tt + 1) * 32 + aC0;
#pragma unroll
            for (int q = 0; q < 4; q++) {
                float4 v = aOK ? *(const float4*)(ap + q * 4) : make_float4(0.f, 0.f, 0.f, 0.f);
                aSt[q * 4 + 0] = v.x; aSt[q * 4 + 1] = v.y;
                aSt[q * 4 + 2] = v.z; aSt[q * 4 + 3] = v.w;
            }
            const float* bp = B + (size_t)((tt + 1) * 32 + bRow) * M + gColB;
#pragma unroll
            for (int q = 0; q < 2; q++) {
                float4 v = bOK ? *(const float4*)(bp + q * 4) : make_float4(0.f, 0.f, 0.f, 0.f);
                bSt[q * 4 + 0] = v.x; bSt[q * 4 + 1] = v.y;
                bSt[q * 4 + 2] = v.z; bSt[q * 4 + 3] = v.w;
            }
        }

        // compute on current smem tile
        int mbase = warp_m * 32;
        int nbase = warp_n * 32;
#pragma unroll
        for (int k8 = 0; k8 < 32; k8 += 8) {
            unsigned int af[2][4], bf[4][2];
#pragma unroll
            for (int im = 0; im < 2; im++) {
                int mr = mbase + im * 16 + groupID;
                af[im][0] = As[k8 + tig][mr];
                af[im][1] = As[k8 + tig][mr + 8];
                af[im][2] = As[k8 + tig + 4][mr];
                af[im][3] = As[k8 + tig + 4][mr + 8];
            }
#pragma unroll
            for (int in_ = 0; in_ < 4; in_++) {
                int nc = nbase + in_ * 8 + groupID;
                bf[in_][0] = Bs[k8 + tig][nc];
                bf[in_][1] = Bs[k8 + tig + 4][nc];
            }
#pragma unroll
            for (int im = 0; im < 2; im++)
#pragma unroll
                for (int in_ = 0; in_ < 4; in_++)
                    mma_tf32(acc[im][in_], af[im], bf[in_]);
        }

        if (tt + 1 < T) {
            __syncthreads();
#pragma unroll
            for (int i = 0; i < 16; i++) As[aC0 + i][aRow] = f2tf32(aSt[i]);
#pragma unroll
            for (int i = 0; i < 8; i++)  Bs[bRow][bC0 + i] = f2tf32(bSt[i]);
            __syncthreads();
        }
    }

    // ---- epilogue ----
#pragma unroll
    for (int im = 0; im < 2; im++) {
        int r_ = row0 + warp_m * 32 + im * 16 + groupID;
#pragma unroll
        for (int in_ = 0; in_ < 4; in_++) {
            int c_ = col0 + warp_n * 32 + in_ * 8 + tig * 2;
            if (c_ < M) {
                if (r_ < N)
                    *(float2*)(C + (size_t)r_ * M + c_) =
                        make_float2(acc[im][in_][0], acc[im][in_][1]);
                if (r_ + 8 < N)
                    *(float2*)(C + (size_t)(r_ + 8) * M + c_) =
                        make_float2(acc[im][in_][2], acc[im][in_][3]);
            }
        }
    }
}

// ---------------- attention coefficients: a_src/a_dst [N,H] ----------------
__global__ void att_kernel(const float* __restrict__ att_s, const float* __restrict__ att_d,
                           int N, int C) {
    int warp = (blockIdx.x * blockDim.x + threadIdx.x) >> 5;
    int lane = threadIdx.x & 31;
    int total = N * 4;
    if (warp >= total) return;
    int n = warp >> 2, hh = warp & 3;
    const float* hp = g_h + (size_t)n * 4 * C + hh * C;
    float s1 = 0.f, s2 = 0.f;
    for (int c = lane; c < C; c += 32) {
        float v = hp[c];
        s1 += v * att_s[hh * C + c];
        s2 += v * att_d[hh * C + c];
    }
#pragma unroll
    for (int o = 16; o; o >>= 1) {
        s1 += __shfl_xor_sync(0xffffffffu, s1, o);
        s2 += __shfl_xor_sync(0xffffffffu, s2, o);
    }
    if (lane == 0) {
        g_asrc[n * 4 + hh] = s1;
        g_adst[n * 4 + hh] = s2;
    }
}

// ---------------- aggregation: warp per dst, CSR, register accumulation ----
__global__ void agg_kernel(const float* __restrict__ bias, float* __restrict__ out_ext,
                           int use_ext, int N, int HC, int C, int do_relu) {
    float* out = use_ext ? out_ext : g_out1;
    int warp = (blockIdx.x * blockDim.x + threadIdx.x) >> 5;
    int lane = threadIdx.x & 31;
    if (warp >= N) return;
    int d = warp;
    int beg = g_off[d], end = g_off[d + 1];
    float4 ad = *(const float4*)(g_adst + d * 4);

    // pass 1: exp(leakyrelu) per edge per head, denominators
    float den0 = 0.f, den1 = 0.f, den2 = 0.f, den3 = 0.f;
    for (int i = beg + lane; i < end; i += 32) {
        int s = g_col[i];
        float4 as = *(const float4*)(g_asrc + s * 4);
        float e0 = as.x + ad.x; e0 = e0 > 0.f ? e0 : 0.2f * e0; e0 = __expf(e0);
        float e1 = as.y + ad.y; e1 = e1 > 0.f ? e1 : 0.2f * e1; e1 = __expf(e1);
        float e2 = as.z + ad.z; e2 = e2 > 0.f ? e2 : 0.2f * e2; e2 = __expf(e2);
        float e3 = as.w + ad.w; e3 = e3 > 0.f ? e3 : 0.2f * e3; e3 = __expf(e3);
        *(float4*)(g_ebuf + (size_t)i * 4) = make_float4(e0, e1, e2, e3);
        den0 += e0; den1 += e1; den2 += e2; den3 += e3;
    }
#pragma unroll
    for (int o = 16; o; o >>= 1) {
        den0 += __shfl_xor_sync(0xffffffffu, den0, o);
        den1 += __shfl_xor_sync(0xffffffffu, den1, o);
        den2 += __shfl_xor_sync(0xffffffffu, den2, o);
        den3 += __shfl_xor_sync(0xffffffffu, den3, o);
    }
    float r0 = 1.f / den0, r1 = 1.f / den1, r2 = 1.f / den2, r3 = 1.f / den3;

    // per-lane feature mapping (HC >= 128 guaranteed: 256 or 160)
    int j0 = lane * 4;
    int h0 = j0 / C;
    int j1 = 128 + lane * 4;
    bool has1 = (j1 < HC);
    int h1 = has1 ? (j1 / C) : 0;

    float4 acc0 = make_float4(0.f, 0.f, 0.f, 0.f);
    float4 acc1 = make_float4(0.f, 0.f, 0.f, 0.f);

    for (int i = beg; i < end; i++) {
        int s = g_col[i];                                  // uniform across warp
        float4 e = *(const float4*)(g_ebuf + (size_t)i * 4);
        float a0 = e.x * r0, a1 = e.y * r1, a2 = e.z * r2, a3 = e.w * r3;
        float aa = h0 == 0 ? a0 : (h0 == 1 ? a1 : (h0 == 2 ? a2 : a3));
        const float* hp = g_h + (size_t)s * HC;
        float4 v0 = *(const float4*)(hp + j0);
        acc0.x += aa * v0.x; acc0.y += aa * v0.y;
        acc0.z += aa * v0.z; acc0.w += aa * v0.w;
        if (has1) {
            float ab = h1 == 0 ? a0 : (h1 == 1 ? a1 : (h1 == 2 ? a2 : a3));
            float4 v1 = *(const float4*)(hp + j1);
            acc1.x += ab * v1.x; acc1.y += ab * v1.y;
            acc1.z += ab * v1.z; acc1.w += ab * v1.w;
        }
    }

    float4 b0 = *(const float4*)(bias + j0);
    acc0.x += b0.x; acc0.y += b0.y; acc0.z += b0.z; acc0.w += b0.w;
    if (do_relu) {
        acc0.x = fmaxf(acc0.x, 0.f); acc0.y = fmaxf(acc0.y, 0.f);
        acc0.z = fmaxf(acc0.z, 0.f); acc0.w = fmaxf(acc0.w, 0.f);
    }
    *(float4*)(out + (size_t)d * HC + j0) = acc0;
    if (has1) {
        float4 b1 = *(const float4*)(bias + j1);
        acc1.x += b1.x; acc1.y += b1.y; acc1.z += b1.z; acc1.w += b1.w;
        if (do_relu) {
            acc1.x = fmaxf(acc1.x, 0.f); acc1.y = fmaxf(acc1.y, 0.f);
            acc1.z = fmaxf(acc1.z, 0.f); acc1.w = fmaxf(acc1.w, 0.f);
        }
        *(float4*)(out + (size_t)d * HC + j1) = acc1;
    }
}

// ---------------- launch ----------------
extern "C" void kernel_launch(void* const* d_in, const int* in_sizes, int n_in,
                              void* d_out, int out_size) {
    const float* x   = (const float*)d_in[0];
    const void*  ei  = d_in[1];
    const float* W1  = (const float*)d_in[2];
    const float* as1 = (const float*)d_in[3];
    const float* ad1 = (const float*)d_in[4];
    const float* b1  = (const float*)d_in[5];
    const float* W2  = (const float*)d_in[6];
    const float* as2 = (const float*)d_in[7];
    const float* ad2 = (const float*)d_in[8];
    const float* b2  = (const float*)d_in[9];

    int E = in_sizes[1] / 2;
    int HC1 = in_sizes[5];          // b1 length (256)
    int HC2 = in_sizes[9];          // b2 length (160)
    int F = in_sizes[2] / HC1;      // 128
    int N = in_sizes[0] / F;        // 50000
    int C1 = HC1 / 4;
    int C2 = HC2 / 4;

    // dtype detection for edge_index
    detect_kernel<<<1, 256>>>((const unsigned int*)ei, E);

    // column stats + standardize
    int nb = 200;
    int rowsPer = ceil_div(N, nb);
    colstats1<<<nb, FIN>>>(x, N, rowsPer);
    colstats2<<<1, FIN>>>(N, nb);
    standardize_kernel<<<ceil_div(N * (F / 4), 256), 256>>>(x, N);

    // CSR build (shared by both layers)
    csr_init<<<ceil_div(N, 256), 256>>>(N);
    csr_count<<<ceil_div(E, 256), 256>>>(ei, E);
    csr_scan<<<1, 1024>>>(N);
    csr_scatter<<<ceil_div(E + N, 256), 256>>>(ei, E, N);

    // ---- layer 1 ----
    {
        dim3 grid(ceil_div(N, 128), ceil_div(HC1, 64));
        gemm_tf32_kernel<<<grid, 256>>>(0, W1, N, F, HC1);
    }
    att_kernel<<<ceil_div(N * 4, 8), 256>>>(as1, ad1, N, C1);
    agg_kernel<<<ceil_div(N, 8), 256>>>(b1, nullptr, 0, N, HC1, C1, 1);

    // ---- layer 2 ----
    {
        dim3 grid(ceil_div(N, 128), ceil_div(HC2, 64));
        gemm_tf32_kernel<<<grid, 256>>>(1, W2, N, HC1, HC2);
    }
    att_kernel<<<ceil_div(N * 4, 8), 256>>>(as2, ad2, N, C2);
    agg_kernel<<<ceil_div(N, 8), 256>>>(b2, (float*)d_out, 1, N, HC2, C2, 0);
}

// round 8
// speedup vs baseline: 1.2027x; 1.0220x over previous
#include <cuda_runtime.h>
#include <cuda_fp16.h>
#include <math.h>

// ---------------- problem capacity constants ----------------
#define MAXN 50000
#define MAXE 800000
#define MAXEL (MAXE + MAXN)   // edges + self loops
#define FIN 128
#define HC1MAX 256

// ---------------- device scratch (no allocations allowed) ----------------
__device__ float  g_h[MAXN * HC1MAX];        // GEMM output (h) fp32, reused per layer
__device__ __half g_h16[MAXN * HC1MAX];      // fp16 copy of h for agg gather
__device__ float  g_out1[MAXN * HC1MAX];     // layer1 output (post relu)
__device__ float  g_asrc[MAXN * 4];
__device__ float  g_adst[MAXN * 4];
__device__ int    g_counts[MAXN];
__device__ int    g_off[MAXN + 1];
__device__ int    g_cursor[MAXN];
__device__ int    g_col[MAXEL];
__device__ float  g_part[256 * 260];         // column-stat partials
__device__ float  g_mean[FIN];
__device__ float  g_istd[FIN];
__device__ int    g_is64;

static inline int ceil_div(int a, int b) { return (a + b - 1) / b; }

// ---------------- edge index dtype detection ----------------
__global__ void detect_kernel(const unsigned int* p, int E) {
    __shared__ unsigned int acc;
    if (threadIdx.x == 0) acc = 0u;
    __syncthreads();
    int n = E < 1024 ? E : 1024;
    unsigned int v = 0;
    for (int i = threadIdx.x; i < n; i += blockDim.x) v |= p[2 * i + 1];
    atomicOr(&acc, v);
    __syncthreads();
    if (threadIdx.x == 0) g_is64 = (acc == 0u) ? 1 : 0;
}

__device__ __forceinline__ void get_edge(const void* ei, int E, int k, int& s, int& d) {
    if (g_is64) {
        const long long* p = (const long long*)ei;
        s = (int)p[k]; d = (int)p[E + k];
    } else {
        const int* p = (const int*)ei;
        s = p[k]; d = p[E + k];
    }
}

// ---------------- column stats (mean, std ddof=1) ----------------
__global__ void colstats1(const float* __restrict__ x, int N, int rowsPer) {
    int f = threadIdx.x;           // FIN threads
    int b = blockIdx.x;
    int r0 = b * rowsPer;
    int r1 = r0 + rowsPer; if (r1 > N) r1 = N;
    float s = 0.f, s2 = 0.f;
    for (int r = r0; r < r1; r++) {
        float v = x[(size_t)r * FIN + f];
        s += v; s2 += v * v;
    }
    g_part[b * 2 * FIN + f] = s;
    g_part[b * 2 * FIN + FIN + f] = s2;
}

__global__ void colstats2(int N, int nb) {
    int f = threadIdx.x;
    double s = 0.0, s2 = 0.0;
    for (int b = 0; b < nb; b++) {
        s  += (double)g_part[b * 2 * FIN + f];
        s2 += (double)g_part[b * 2 * FIN + FIN + f];
    }
    double mean = s / (double)N;
    double var = (s2 - s * s / (double)N) / (double)(N - 1);
    g_mean[f] = (float)mean;
    g_istd[f] = (float)(1.0 / sqrt(var));
}

// ---------------- CSR build (by dst, self-loops included) ----------------
__global__ void csr_init(int N) {
    int i = blockIdx.x * blockDim.x + threadIdx.x;
    if (i < N) g_counts[i] = 1;   // self loop
}

__global__ void csr_count(const void* ei, int E) {
    int k = blockIdx.x * blockDim.x + threadIdx.x;
    if (k >= E) return;
    int s, d; get_edge(ei, E, k, s, d);
    atomicAdd(&g_counts[d], 1);
}

__global__ void csr_scan(int N) {
    __shared__ int sm[1024];
    int t = threadIdx.x;
    int chunk = (N + 1023) / 1024;
    int start = t * chunk;
    int end = start + chunk; if (end > N) end = N;
    int sum = 0;
    for (int i = start; i < end; i++) sum += g_counts[i];
    sm[t] = sum;
    __syncthreads();
    for (int o = 1; o < 1024; o <<= 1) {
        int v = (t >= o) ? sm[t - o] : 0;
        __syncthreads();
        sm[t] += v;
        __syncthreads();
    }
    int run = sm[t] - sum;   // exclusive
    for (int i = start; i < end; i++) {
        g_off[i] = run;
        g_cursor[i] = run;
        run += g_counts[i];
    }
    if (t == 1023) g_off[N] = sm[1023];
}

__global__ void csr_scatter(const void* ei, int E, int N) {
    int k = blockIdx.x * blockDim.x + threadIdx.x;
    if (k >= E + N) return;
    int s, d;
    if (k < E) get_edge(ei, E, k, s, d);
    else { s = k - E; d = s; }
    int pos = atomicAdd(&g_cursor[d], 1);
    g_col[pos] = s;
}

// ---------------- tf32 tensor-core GEMM ----------------
// C[N,M] = A[N,K] @ B[K,M].  BM=128, BN=64, BK=32, 256 threads (8 warps, 4x2).
// Warp tile 32x32 = 2x4 m16n8k8 mma.  asel==0: A = x with fused standardization.
// Epilogue writes fp32 C (g_h) and fp16 copy (g_h16).

__device__ __forceinline__ unsigned int f2tf32(float f) {
    unsigned int r;
    asm("cvt.rna.tf32.f32 %0, %1;" : "=r"(r) : "f"(f));
    return r;
}

__device__ __forceinline__ void mma_tf32(float* c, const unsigned int* a, const unsigned int* b) {
    asm volatile(
        "mma.sync.aligned.m16n8k8.row.col.f32.tf32.tf32.f32 "
        "{%0,%1,%2,%3}, {%4,%5,%6,%7}, {%8,%9}, {%0,%1,%2,%3};\n"
        : "+f"(c[0]), "+f"(c[1]), "+f"(c[2]), "+f"(c[3])
        : "r"(a[0]), "r"(a[1]), "r"(a[2]), "r"(a[3]), "r"(b[0]), "r"(b[1]));
}

__global__ __launch_bounds__(256, 2)
void gemm_tf32_kernel(int asel, const float* __restrict__ Aext,
                      const float* __restrict__ B, int N, int K, int M) {
    const float* __restrict__ A = asel ? g_out1 : Aext;
    float* __restrict__ C = g_h;

    __shared__ unsigned int As[32][136];   // [k][m], m-pad 128->136
    __shared__ unsigned int Bs[32][72];    // [k][n], n-pad 64->72

    int t = threadIdx.x;
    int lane = t & 31;
    int warp = t >> 5;
    int groupID = lane >> 2;
    int tig = lane & 3;
    int warp_m = warp >> 1;   // 0..3
    int warp_n = warp & 1;    // 0..1

    int row0 = blockIdx.x * 128;
    int col0 = blockIdx.y * 64;

    int aRow = t >> 1;          // 0..127
    int aC0  = (t & 1) * 16;    // 0 or 16
    int bRow = t >> 3;          // 0..31
    int bC0  = (t & 7) * 8;     // 0..56

    float acc[2][4][4];
#pragma unroll
    for (int i = 0; i < 2; i++)
#pragma unroll
        for (int j = 0; j < 4; j++)
#pragma unroll
            for (int c = 0; c < 4; c++) acc[i][j][c] = 0.f;

    int T = K >> 5;

    float aSt[16];
    float bSt[8];

    int gRowA = row0 + aRow;
    bool aOK = gRowA < N;
    int gColB = col0 + bC0;
    bool bOK = gColB < M;

    // ---- stage tile 0 ----
    {
        const float* ap = A + (size_t)gRowA * K + aC0;
#pragma unroll
        for (int q = 0; q < 4; q++) {
            float4 v = aOK ? *(const float4*)(ap + q * 4) : make_float4(0.f, 0.f, 0.f, 0.f);
            if (!asel) {
                int c = aC0 + q * 4;
                float4 mn = *(const float4*)(g_mean + c);
                float4 is = *(const float4*)(g_istd + c);
                v.x = (v.x - mn.x) * is.x; v.y = (v.y - mn.y) * is.y;
                v.z = (v.z - mn.z) * is.z; v.w = (v.w - mn.w) * is.w;
            }
            aSt[q * 4 + 0] = v.x; aSt[q * 4 + 1] = v.y;
            aSt[q * 4 + 2] = v.z; aSt[q * 4 + 3] = v.w;
        }
        const float* bp = B + (size_t)bRow * M + gColB;
#pragma unroll
        for (int q = 0; q < 2; q++) {
            float4 v = bOK ? *(const float4*)(bp + q * 4) : make_float4(0.f, 0.f, 0.f, 0.f);
            bSt[q * 4 + 0] = v.x; bSt[q * 4 + 1] = v.y;
            bSt[q * 4 + 2] = v.z; bSt[q * 4 + 3] = v.w;
        }
    }
#pragma unroll
    for (int i = 0; i < 16; i++) As[aC0 + i][aRow] = f2tf32(aSt[i]);
#pragma unroll
    for (int i = 0; i < 8; i++)  Bs[bRow][bC0 + i] = f2tf32(bSt[i]);
    __syncthreads();

    for (int tt = 0; tt < T; tt++) {
        if (tt + 1 < T) {
            int kbase = (tt + 1) * 32;
            const float* ap = A + (size_t)gRowA * K + kbase + aC0;
#pragma unroll
            for (int q = 0; q < 4; q++) {
                float4 v = aOK ? *(const float4*)(ap + q * 4) : make_float4(0.f, 0.f, 0.f, 0.f);
                if (!asel) {
                    int c = kbase + aC0 + q * 4;
                    float4 mn = *(const float4*)(g_mean + c);
                    float4 is = *(const float4*)(g_istd + c);
                    v.x = (v.x - mn.x) * is.x; v.y = (v.y - mn.y) * is.y;
                    v.z = (v.z - mn.z) * is.z; v.w = (v.w - mn.w) * is.w;
                }
                aSt[q * 4 + 0] = v.x; aSt[q * 4 + 1] = v.y;
                aSt[q * 4 + 2] = v.z; aSt[q * 4 + 3] = v.w;
            }
            const float* bp = B + (size_t)(kbase + bRow) * M + gColB;
#pragma unroll
            for (int q = 0; q < 2; q++) {
                float4 v = bOK ? *(const float4*)(bp + q * 4) : make_float4(0.f, 0.f, 0.f, 0.f);
                bSt[q * 4 + 0] = v.x; bSt[q * 4 + 1] = v.y;
                bSt[q * 4 + 2] = v.z; bSt[q * 4 + 3] = v.w;
            }
        }

        int mbase = warp_m * 32;
        int nbase = warp_n * 32;
#pragma unroll
        for (int k8 = 0; k8 < 32; k8 += 8) {
            unsigned int af[2][4], bf[4][2];
#pragma unroll
            for (int im = 0; im < 2; im++) {
                int mr = mbase + im * 16 + groupID;
                af[im][0] = As[k8 + tig][mr];
                af[im][1] = As[k8 + tig][mr + 8];
                af[im][2] = As[k8 + tig + 4][mr];
                af[im][3] = As[k8 + tig + 4][mr + 8];
            }
#pragma unroll
            for (int in_ = 0; in_ < 4; in_++) {
                int nc = nbase + in_ * 8 + groupID;
                bf[in_][0] = Bs[k8 + tig][nc];
                bf[in_][1] = Bs[k8 + tig + 4][nc];
            }
#pragma unroll
            for (int im = 0; im < 2; im++)
#pragma unroll
                for (int in_ = 0; in_ < 4; in_++)
                    mma_tf32(acc[im][in_], af[im], bf[in_]);
        }

        if (tt + 1 < T) {
            __syncthreads();
#pragma unroll
            for (int i = 0; i < 16; i++) As[aC0 + i][aRow] = f2tf32(aSt[i]);
#pragma unroll
            for (int i = 0; i < 8; i++)  Bs[bRow][bC0 + i] = f2tf32(bSt[i]);
            __syncthreads();
        }
    }

    // ---- epilogue: fp32 + fp16 copies ----
#pragma unroll
    for (int im = 0; im < 2; im++) {
        int r_ = row0 + warp_m * 32 + im * 16 + groupID;
#pragma unroll
        for (int in_ = 0; in_ < 4; in_++) {
            int c_ = col0 + warp_n * 32 + in_ * 8 + tig * 2;
            if (c_ < M) {
                if (r_ < N) {
                    *(float2*)(C + (size_t)r_ * M + c_) =
                        make_float2(acc[im][in_][0], acc[im][in_][1]);
                    *(half2*)(g_h16 + (size_t)r_ * M + c_) =
                        __floats2half2_rn(acc[im][in_][0], acc[im][in_][1]);
                }
                if (r_ + 8 < N) {
                    *(float2*)(C + (size_t)(r_ + 8) * M + c_) =
                        make_float2(acc[im][in_][2], acc[im][in_][3]);
                    *(half2*)(g_h16 + (size_t)(r_ + 8) * M + c_) =
                        __floats2half2_rn(acc[im][in_][2], acc[im][in_][3]);
                }
            }
        }
    }
}

// ---------------- attention coefficients: a_src/a_dst [N,H] ----------------
__global__ void att_kernel(const float* __restrict__ att_s, const float* __restrict__ att_d,
                           int N, int C) {
    int warp = (blockIdx.x * blockDim.x + threadIdx.x) >> 5;
    int lane = threadIdx.x & 31;
    int total = N * 4;
    if (warp >= total) return;
    int n = warp >> 2, hh = warp & 3;
    const float* hp = g_h + (size_t)n * 4 * C + hh * C;
    float s1 = 0.f, s2 = 0.f;
    for (int c = lane; c < C; c += 32) {
        float v = hp[c];
        s1 += v * att_s[hh * C + c];
        s2 += v * att_d[hh * C + c];
    }
#pragma unroll
    for (int o = 16; o; o >>= 1) {
        s1 += __shfl_xor_sync(0xffffffffu, s1, o);
        s2 += __shfl_xor_sync(0xffffffffu, s2, o);
    }
    if (lane == 0) {
        g_asrc[n * 4 + hh] = s1;
        g_adst[n * 4 + hh] = s2;
    }
}

// ---------------- single-pass aggregation: warp per dst ----------------
// out[d] = (sum_i e_i * h16[s_i]) / (sum_i e_i) + bias  (softmax denominator factored)
__global__ void agg_kernel(const float* __restrict__ bias, float* __restrict__ out_ext,
                           int use_ext, int N, int HC, int C, int do_relu) {
    float* out = use_ext ? out_ext : g_out1;
    int warp = (blockIdx.x * blockDim.x + threadIdx.x) >> 5;
    int lane = threadIdx.x & 31;
    if (warp >= N) return;
    int d = warp;
    int beg = g_off[d], end = g_off[d + 1];
    float4 ad = *(const float4*)(g_adst + d * 4);

    int j0 = lane * 8;                 // 8 halves per lane
    bool act = j0 < HC;                // HC=256: all lanes; HC=160: lanes 0..19
    int h0 = act ? (j0 / C) : 0;       // head for this lane's block (8 | C)

    float acc[8];
#pragma unroll
    for (int q = 0; q < 8; q++) acc[q] = 0.f;
    float den0 = 0.f, den1 = 0.f, den2 = 0.f, den3 = 0.f;

    for (int i = beg; i < end; i++) {
        int s = g_col[i];                                   // warp-uniform
        float4 as = *(const float4*)(g_asrc + s * 4);       // warp-uniform (broadcast)
        float e0 = as.x + ad.x; e0 = e0 > 0.f ? e0 : 0.2f * e0; e0 = __expf(e0);
        float e1 = as.y + ad.y; e1 = e1 > 0.f ? e1 : 0.2f * e1; e1 = __expf(e1);
        float e2 = as.z + ad.z; e2 = e2 > 0.f ? e2 : 0.2f * e2; e2 = __expf(e2);
        float e3 = as.w + ad.w; e3 = e3 > 0.f ? e3 : 0.2f * e3; e3 = __expf(e3);
        den0 += e0; den1 += e1; den2 += e2; den3 += e3;

        if (act) {
            float aa = h0 == 0 ? e0 : (h0 == 1 ? e1 : (h0 == 2 ? e2 : e3));
            const __half* hp = g_h16 + (size_t)s * HC + j0;
            uint4 hv = *(const uint4*)hp;
            float2 f0 = __half22float2(*(const half2*)&hv.x);
            float2 f1 = __half22float2(*(const half2*)&hv.y);
            float2 f2 = __half22float2(*(const half2*)&hv.z);
            float2 f3 = __half22float2(*(const half2*)&hv.w);
            acc[0] += aa * f0.x; acc[1] += aa * f0.y;
            acc[2] += aa * f1.x; acc[3] += aa * f1.y;
            acc[4] += aa * f2.x; acc[5] += aa * f2.y;
            acc[6] += aa * f3.x; acc[7] += aa * f3.y;
        }
    }

    if (act) {
        float dd = h0 == 0 ? den0 : (h0 == 1 ? den1 : (h0 == 2 ? den2 : den3));
        float r = 1.f / dd;
        float4 b0 = *(const float4*)(bias + j0);
        float4 b1 = *(const float4*)(bias + j0 + 4);
        float4 o0, o1;
        o0.x = acc[0] * r + b0.x; o0.y = acc[1] * r + b0.y;
        o0.z = acc[2] * r + b0.z; o0.w = acc[3] * r + b0.w;
        o1.x = acc[4] * r + b1.x; o1.y = acc[5] * r + b1.y;
        o1.z = acc[6] * r + b1.z; o1.w = acc[7] * r + b1.w;
        if (do_relu) {
            o0.x = fmaxf(o0.x, 0.f); o0.y = fmaxf(o0.y, 0.f);
            o0.z = fmaxf(o0.z, 0.f); o0.w = fmaxf(o0.w, 0.f);
            o1.x = fmaxf(o1.x, 0.f); o1.y = fmaxf(o1.y, 0.f);
            o1.z = fmaxf(o1.z, 0.f); o1.w = fmaxf(o1.w, 0.f);
        }
        *(float4*)(out + (size_t)d * HC + j0)     = o0;
        *(float4*)(out + (size_t)d * HC + j0 + 4) = o1;
    }
}

// ---------------- launch ----------------
extern "C" void kernel_launch(void* const* d_in, const int* in_sizes, int n_in,
                              void* d_out, int out_size) {
    const float* x   = (const float*)d_in[0];
    const void*  ei  = d_in[1];
    const float* W1  = (const float*)d_in[2];
    const float* as1 = (const float*)d_in[3];
    const float* ad1 = (const float*)d_in[4];
    const float* b1  = (const float*)d_in[5];
    const float* W2  = (const float*)d_in[6];
    const float* as2 = (const float*)d_in[7];
    const float* ad2 = (const float*)d_in[8];
    const float* b2  = (const float*)d_in[9];

    int E = in_sizes[1] / 2;
    int HC1 = in_sizes[5];          // 256
    int HC2 = in_sizes[9];          // 160
    int F = in_sizes[2] / HC1;      // 128
    int N = in_sizes[0] / F;        // 50000
    int C1 = HC1 / 4;
    int C2 = HC2 / 4;

    detect_kernel<<<1, 256>>>((const unsigned int*)ei, E);

    // column stats (standardization itself is fused into GEMM-1 A-load)
    int nb = 200;
    int rowsPer = ceil_div(N, nb);
    colstats1<<<nb, FIN>>>(x, N, rowsPer);
    colstats2<<<1, FIN>>>(N, nb);

    // CSR build (shared by both layers)
    csr_init<<<ceil_div(N, 256), 256>>>(N);
    csr_count<<<ceil_div(E, 256), 256>>>(ei, E);
    csr_scan<<<1, 1024>>>(N);
    csr_scatter<<<ceil_div(E + N, 256), 256>>>(ei, E, N);

    // ---- layer 1 ----
    {
        dim3 grid(ceil_div(N, 128), ceil_div(HC1, 64));
        gemm_tf32_kernel<<<grid, 256>>>(0, x, W1, N, F, HC1);
    }
    att_kernel<<<ceil_div(N * 4, 8), 256>>>(as1, ad1, N, C1);
    agg_kernel<<<ceil_div(N, 8), 256>>>(b1, nullptr, 0, N, HC1, C1, 1);

    // ---- layer 2 ----
    {
        dim3 grid(ceil_div(N, 128), ceil_div(HC2, 64));
        gemm_tf32_kernel<<<grid, 256>>>(1, nullptr, W2, N, HC1, HC2);
    }
    att_kernel<<<ceil_div(N * 4, 8), 256>>>(as2, ad2, N, C2);
    agg_kernel<<<ceil_div(N, 8), 256>>>(b2, (float*)d_out, 1, N, HC2, C2, 0);
}

// round 9
// speedup vs baseline: 1.5101x; 1.2555x over previous
#include <cuda_runtime.h>
#include <cuda_fp16.h>
#include <math.h>

// ---------------- problem capacity constants ----------------
#define MAXN 50000
#define MAXE 800000
#define MAXEL (MAXE + MAXN)   // edges + self loops
#define FIN 128
#define HC1MAX 256

// ---------------- device scratch (no allocations allowed) ----------------
__device__ float  g_h[MAXN * HC1MAX];        // GEMM output (h) fp32, reused per layer
__device__ __half g_h16[MAXN * HC1MAX];      // fp16 copy of h for agg gather
__device__ float  g_out1[MAXN * HC1MAX];     // layer1 output (post relu)
__device__ float  g_asrc[MAXN * 4];
__device__ float  g_adst[MAXN * 4];
__device__ int    g_counts[MAXN];
__device__ int    g_off[MAXN + 1];
__device__ int    g_cursor[MAXN];
__device__ int    g_col[MAXEL];
__device__ float  g_part[256 * 260];         // column-stat partials
__device__ float  g_mean[FIN];
__device__ float  g_istd[FIN];
__device__ int    g_is64;

static inline int ceil_div(int a, int b) { return (a + b - 1) / b; }

// ---------------- prep: edge-dtype detect + zero CSR counts (merged) ----------
__global__ void prep_kernel(const unsigned int* p, int E, int N) {
    int b = blockIdx.x;
    if (b == gridDim.x - 1) {
        // detect int64 vs int32 edge_index
        __shared__ unsigned int acc;
        if (threadIdx.x == 0) acc = 0u;
        __syncthreads();
        int n = E < 1024 ? E : 1024;
        unsigned int v = 0;
        for (int i = threadIdx.x; i < n; i += blockDim.x) v |= p[2 * i + 1];
        atomicOr(&acc, v);
        __syncthreads();
        if (threadIdx.x == 0) g_is64 = (acc == 0u) ? 1 : 0;
    } else {
        int i = b * blockDim.x + threadIdx.x;
        if (i < N) g_counts[i] = 1;   // self loop
    }
}

__device__ __forceinline__ void get_edge(const void* ei, int E, int k, int& s, int& d) {
    if (g_is64) {
        const long long* p = (const long long*)ei;
        s = (int)p[k]; d = (int)p[E + k];
    } else {
        const int* p = (const int*)ei;
        s = p[k]; d = p[E + k];
    }
}

// ---------------- column stats (mean, std ddof=1) ----------------
__global__ void colstats1(const float* __restrict__ x, int N, int rowsPer) {
    int f = threadIdx.x;           // FIN threads
    int b = blockIdx.x;
    int r0 = b * rowsPer;
    int r1 = r0 + rowsPer; if (r1 > N) r1 = N;
    float s = 0.f, s2 = 0.f;
    for (int r = r0; r < r1; r++) {
        float v = x[(size_t)r * FIN + f];
        s += v; s2 += v * v;
    }
    g_part[b * 2 * FIN + f] = s;
    g_part[b * 2 * FIN + FIN + f] = s2;
}

__global__ void colstats2(int N, int nb) {
    int f = threadIdx.x;
    double s = 0.0, s2 = 0.0;
    for (int b = 0; b < nb; b++) {
        s  += (double)g_part[b * 2 * FIN + f];
        s2 += (double)g_part[b * 2 * FIN + FIN + f];
    }
    double mean = s / (double)N;
    double var = (s2 - s * s / (double)N) / (double)(N - 1);
    g_mean[f] = (float)mean;
    g_istd[f] = (float)(1.0 / sqrt(var));
}

// ---------------- CSR build (by dst, self-loops included) ----------------
__global__ void csr_count(const void* ei, int E) {
    int k = blockIdx.x * blockDim.x + threadIdx.x;
    if (k >= E) return;
    int s, d; get_edge(ei, E, k, s, d);
    atomicAdd(&g_counts[d], 1);
}

__global__ void csr_scan(int N) {
    __shared__ int sm[1024];
    int t = threadIdx.x;
    int chunk = (N + 1023) / 1024;
    int start = t * chunk;
    int end = start + chunk; if (end > N) end = N;
    int sum = 0;
    for (int i = start; i < end; i++) sum += g_counts[i];
    sm[t] = sum;
    __syncthreads();
    for (int o = 1; o < 1024; o <<= 1) {
        int v = (t >= o) ? sm[t - o] : 0;
        __syncthreads();
        sm[t] += v;
        __syncthreads();
    }
    int run = sm[t] - sum;   // exclusive
    for (int i = start; i < end; i++) {
        g_off[i] = run;
        g_cursor[i] = run;
        run += g_counts[i];
    }
    if (t == 1023) g_off[N] = sm[1023];
}

__global__ void csr_scatter(const void* ei, int E, int N) {
    int k = blockIdx.x * blockDim.x + threadIdx.x;
    if (k >= E + N) return;
    int s, d;
    if (k < E) get_edge(ei, E, k, s, d);
    else { s = k - E; d = s; }
    int pos = atomicAdd(&g_cursor[d], 1);
    g_col[pos] = s;
}

// ---------------- tf32 tensor-core GEMM ----------------
// C[N,M] = A[N,K] @ B[K,M].  BM=128, BN=64, BK=32, 256 threads (8 warps, 4x2).
// Warp tile 32x32 = 2x4 m16n8k8 mma.  asel==0: A = x with fused standardization.
// Epilogue writes fp32 C (g_h) and fp16 copy (g_h16).

__device__ __forceinline__ unsigned int f2tf32(float f) {
    unsigned int r;
    asm("cvt.rna.tf32.f32 %0, %1;" : "=r"(r) : "f"(f));
    return r;
}

__device__ __forceinline__ void mma_tf32(float* c, const unsigned int* a, const unsigned int* b) {
    asm volatile(
        "mma.sync.aligned.m16n8k8.row.col.f32.tf32.tf32.f32 "
        "{%0,%1,%2,%3}, {%4,%5,%6,%7}, {%8,%9}, {%0,%1,%2,%3};\n"
        : "+f"(c[0]), "+f"(c[1]), "+f"(c[2]), "+f"(c[3])
        : "r"(a[0]), "r"(a[1]), "r"(a[2]), "r"(a[3]), "r"(b[0]), "r"(b[1]));
}

__global__ __launch_bounds__(256, 2)
void gemm_tf32_kernel(int asel, const float* __restrict__ Aext,
                      const float* __restrict__ B, int N, int K, int M) {
    const float* __restrict__ A = asel ? g_out1 : Aext;
    float* __restrict__ C = g_h;

    __shared__ unsigned int As[32][136];   // [k][m], m-pad 128->136
    __shared__ unsigned int Bs[32][72];    // [k][n], n-pad 64->72

    int t = threadIdx.x;
    int lane = t & 31;
    int warp = t >> 5;
    int groupID = lane >> 2;
    int tig = lane & 3;
    int warp_m = warp >> 1;   // 0..3
    int warp_n = warp & 1;    // 0..1

    int row0 = blockIdx.x * 128;
    int col0 = blockIdx.y * 64;

    int aRow = t >> 1;          // 0..127
    int aC0  = (t & 1) * 16;    // 0 or 16
    int bRow = t >> 3;          // 0..31
    int bC0  = (t & 7) * 8;     // 0..56

    float acc[2][4][4];
#pragma unroll
    for (int i = 0; i < 2; i++)
#pragma unroll
        for (int j = 0; j < 4; j++)
#pragma unroll
            for (int c = 0; c < 4; c++) acc[i][j][c] = 0.f;

    int T = K >> 5;

    float aSt[16];
    float bSt[8];

    int gRowA = row0 + aRow;
    bool aOK = gRowA < N;
    int gColB = col0 + bC0;
    bool bOK = gColB < M;

    // ---- stage tile 0 ----
    {
        const float* ap = A + (size_t)gRowA * K + aC0;
#pragma unroll
        for (int q = 0; q < 4; q++) {
            float4 v = aOK ? *(const float4*)(ap + q * 4) : make_float4(0.f, 0.f, 0.f, 0.f);
            if (!asel) {
                int c = aC0 + q * 4;
                float4 mn = *(const float4*)(g_mean + c);
                float4 is = *(const float4*)(g_istd + c);
                v.x = (v.x - mn.x) * is.x; v.y = (v.y - mn.y) * is.y;
                v.z = (v.z - mn.z) * is.z; v.w = (v.w - mn.w) * is.w;
            }
            aSt[q * 4 + 0] = v.x; aSt[q * 4 + 1] = v.y;
            aSt[q * 4 + 2] = v.z; aSt[q * 4 + 3] = v.w;
        }
        const float* bp = B + (size_t)bRow * M + gColB;
#pragma unroll
        for (int q = 0; q < 2; q++) {
            float4 v = bOK ? *(const float4*)(bp + q * 4) : make_float4(0.f, 0.f, 0.f, 0.f);
            bSt[q * 4 + 0] = v.x; bSt[q * 4 + 1] = v.y;
            bSt[q * 4 + 2] = v.z; bSt[q * 4 + 3] = v.w;
        }
    }
#pragma unroll
    for (int i = 0; i < 16; i++) As[aC0 + i][aRow] = f2tf32(aSt[i]);
#pragma unroll
    for (int i = 0; i < 8; i++)  Bs[bRow][bC0 + i] = f2tf32(bSt[i]);
    __syncthreads();

    for (int tt = 0; tt < T; tt++) {
        if (tt + 1 < T) {
            int kbase = (tt + 1) * 32;
            const float* ap = A + (size_t)gRowA * K + kbase + aC0;
#pragma unroll
            for (int q = 0; q < 4; q++) {
                float4 v = aOK ? *(const float4*)(ap + q * 4) : make_float4(0.f, 0.f, 0.f, 0.f);
                if (!asel) {
                    int c = kbase + aC0 + q * 4;
                    float4 mn = *(const float4*)(g_mean + c);
                    float4 is = *(const float4*)(g_istd + c);
                    v.x = (v.x - mn.x) * is.x; v.y = (v.y - mn.y) * is.y;
                    v.z = (v.z - mn.z) * is.z; v.w = (v.w - mn.w) * is.w;
                }
                aSt[q * 4 + 0] = v.x; aSt[q * 4 + 1] = v.y;
                aSt[q * 4 + 2] = v.z; aSt[q * 4 + 3] = v.w;
            }
            const float* bp = B + (size_t)(kbase + bRow) * M + gColB;
#pragma unroll
            for (int q = 0; q < 2; q++) {
                float4 v = bOK ? *(const float4*)(bp + q * 4) : make_float4(0.f, 0.f, 0.f, 0.f);
                bSt[q * 4 + 0] = v.x; bSt[q * 4 + 1] = v.y;
                bSt[q * 4 + 2] = v.z; bSt[q * 4 + 3] = v.w;
            }
        }

        int mbase = warp_m * 32;
        int nbase = warp_n * 32;
#pragma unroll
        for (int k8 = 0; k8 < 32; k8 += 8) {
            unsigned int af[2][4], bf[4][2];
#pragma unroll
            for (int im = 0; im < 2; im++) {
                int mr = mbase + im * 16 + groupID;
                af[im][0] = As[k8 + tig][mr];
                af[im][1] = As[k8 + tig][mr + 8];
                af[im][2] = As[k8 + tig + 4][mr];
                af[im][3] = As[k8 + tig + 4][mr + 8];
            }
#pragma unroll
            for (int in_ = 0; in_ < 4; in_++) {
                int nc = nbase + in_ * 8 + groupID;
                bf[in_][0] = Bs[k8 + tig][nc];
                bf[in_][1] = Bs[k8 + tig + 4][nc];
            }
#pragma unroll
            for (int im = 0; im < 2; im++)
#pragma unroll
                for (int in_ = 0; in_ < 4; in_++)
                    mma_tf32(acc[im][in_], af[im], bf[in_]);
        }

        if (tt + 1 < T) {
            __syncthreads();
#pragma unroll
            for (int i = 0; i < 16; i++) As[aC0 + i][aRow] = f2tf32(aSt[i]);
#pragma unroll
            for (int i = 0; i < 8; i++)  Bs[bRow][bC0 + i] = f2tf32(bSt[i]);
            __syncthreads();
        }
    }

    // ---- epilogue: fp32 + fp16 copies ----
#pragma unroll
    for (int im = 0; im < 2; im++) {
        int r_ = row0 + warp_m * 32 + im * 16 + groupID;
#pragma unroll
        for (int in_ = 0; in_ < 4; in_++) {
            int c_ = col0 + warp_n * 32 + in_ * 8 + tig * 2;
            if (c_ < M) {
                if (r_ < N) {
                    *(float2*)(C + (size_t)r_ * M + c_) =
                        make_float2(acc[im][in_][0], acc[im][in_][1]);
                    *(half2*)(g_h16 + (size_t)r_ * M + c_) =
                        __floats2half2_rn(acc[im][in_][0], acc[im][in_][1]);
                }
                if (r_ + 8 < N) {
                    *(float2*)(C + (size_t)(r_ + 8) * M + c_) =
                        make_float2(acc[im][in_][2], acc[im][in_][3]);
                    *(half2*)(g_h16 + (size_t)(r_ + 8) * M + c_) =
                        __floats2half2_rn(acc[im][in_][2], acc[im][in_][3]);
                }
            }
        }
    }
}

// ---------------- attention coefficients: a_src/a_dst [N,H] ----------------
__global__ void att_kernel(const float* __restrict__ att_s, const float* __restrict__ att_d,
                           int N, int C) {
    int warp = (blockIdx.x * blockDim.x + threadIdx.x) >> 5;
    int lane = threadIdx.x & 31;
    int total = N * 4;
    if (warp >= total) return;
    int n = warp >> 2, hh = warp & 3;
    const float* hp = g_h + (size_t)n * 4 * C + hh * C;
    float s1 = 0.f, s2 = 0.f;
    for (int c = lane; c < C; c += 32) {
        float v = hp[c];
        s1 += v * att_s[hh * C + c];
        s2 += v * att_d[hh * C + c];
    }
#pragma unroll
    for (int o = 16; o; o >>= 1) {
        s1 += __shfl_xor_sync(0xffffffffu, s1, o);
        s2 += __shfl_xor_sync(0xffffffffu, s2, o);
    }
    if (lane == 0) {
        g_asrc[n * 4 + hh] = s1;
        g_adst[n * 4 + hh] = s2;
    }
}

// ---------------- single-pass aggregation: warp per dst ----------------
// Chunked: lanes compute e for 32 edges in parallel (expf once per edge, not
// per lane), stash {src, e0..e3} in smem, then the gather loop broadcasts them.
// out[d] = (sum_i e_i * h16[s_i]) / (sum_i e_i) + bias
__global__ __launch_bounds__(256)
void agg_kernel(const float* __restrict__ bias, float* __restrict__ out_ext,
                int use_ext, int N, int HC, int C, int do_relu) {
    __shared__ float sm_e[8][32][4];
    __shared__ int   sm_s[8][32];
    float* out = use_ext ? out_ext : g_out1;
    int w = threadIdx.x >> 5;
    int warp = (blockIdx.x * blockDim.x + threadIdx.x) >> 5;
    int lane = threadIdx.x & 31;
    if (warp >= N) return;
    int d = warp;
    int beg = g_off[d], end = g_off[d + 1];
    float4 ad = *(const float4*)(g_adst + d * 4);

    int j0 = lane * 8;                 // 8 halves per lane
    bool act = j0 < HC;                // HC=256: all lanes; HC=160: lanes 0..19
    int h0 = act ? (j0 / C) : 0;       // head for this lane's block (8 | C)
    const __half* __restrict__ hbase = g_h16 + j0;

    float acc[8];
#pragma unroll
    for (int q = 0; q < 8; q++) acc[q] = 0.f;
    float den0 = 0.f, den1 = 0.f, den2 = 0.f, den3 = 0.f;

    for (int i0 = beg; i0 < end; i0 += 32) {
        // ---- edge-parallel e prep (one edge per lane) ----
        int i = i0 + lane;
        bool ea = i < end;
        int s = ea ? g_col[i] : 0;
        float4 as = *(const float4*)(g_asrc + s * 4);
        float e0 = as.x + ad.x; e0 = e0 > 0.f ? e0 : 0.2f * e0; e0 = __expf(e0);
        float e1 = as.y + ad.y; e1 = e1 > 0.f ? e1 : 0.2f * e1; e1 = __expf(e1);
        float e2 = as.z + ad.z; e2 = e2 > 0.f ? e2 : 0.2f * e2; e2 = __expf(e2);
        float e3 = as.w + ad.w; e3 = e3 > 0.f ? e3 : 0.2f * e3; e3 = __expf(e3);
        if (ea) { den0 += e0; den1 += e1; den2 += e2; den3 += e3; }
        sm_s[w][lane] = s;
        *(float4*)&sm_e[w][lane][0] = make_float4(e0, e1, e2, e3);
        __syncwarp();

        // ---- gather loop over this chunk ----
        int cnt = end - i0; if (cnt > 32) cnt = 32;
        if (act) {
            for (int j = 0; j < cnt; j++) {
                int ss = sm_s[w][j];                    // uniform (broadcast LDS)
                float aa = sm_e[w][j][h0];              // 4-way LDS, conflict-free
                uint4 hv = *(const uint4*)(hbase + (size_t)ss * HC);
                float2 f0 = __half22float2(*(const half2*)&hv.x);
                float2 f1 = __half22float2(*(const half2*)&hv.y);
                float2 f2 = __half22float2(*(const half2*)&hv.z);
                float2 f3 = __half22float2(*(const half2*)&hv.w);
                acc[0] += aa * f0.x; acc[1] += aa * f0.y;
                acc[2] += aa * f1.x; acc[3] += aa * f1.y;
                acc[4] += aa * f2.x; acc[5] += aa * f2.y;
                acc[6] += aa * f3.x; acc[7] += aa * f3.y;
            }
        }
        __syncwarp();
    }

    // warp-reduce denominators (each lane holds partials of its strided edges)
#pragma unroll
    for (int o = 16; o; o >>= 1) {
        den0 += __shfl_xor_sync(0xffffffffu, den0, o);
        den1 += __shfl_xor_sync(0xffffffffu, den1, o);
        den2 += __shfl_xor_sync(0xffffffffu, den2, o);
        den3 += __shfl_xor_sync(0xffffffffu, den3, o);
    }

    if (act) {
        float dd = h0 == 0 ? den0 : (h0 == 1 ? den1 : (h0 == 2 ? den2 : den3));
        float r = 1.f / dd;
        float4 b0 = *(const float4*)(bias + j0);
        float4 b1 = *(const float4*)(bias + j0 + 4);
        float4 o0, o1;
        o0.x = acc[0] * r + b0.x; o0.y = acc[1] * r + b0.y;
        o0.z = acc[2] * r + b0.z; o0.w = acc[3] * r + b0.w;
        o1.x = acc[4] * r + b1.x; o1.y = acc[5] * r + b1.y;
        o1.z = acc[6] * r + b1.z; o1.w = acc[7] * r + b1.w;
        if (do_relu) {
            o0.x = fmaxf(o0.x, 0.f); o0.y = fmaxf(o0.y, 0.f);
            o0.z = fmaxf(o0.z, 0.f); o0.w = fmaxf(o0.w, 0.f);
            o1.x = fmaxf(o1.x, 0.f); o1.y = fmaxf(o1.y, 0.f);
            o1.z = fmaxf(o1.z, 0.f); o1.w = fmaxf(o1.w, 0.f);
        }
        *(float4*)(out + (size_t)d * HC + j0)     = o0;
        *(float4*)(out + (size_t)d * HC + j0 + 4) = o1;
    }
}

// ---------------- launch ----------------
extern "C" void kernel_launch(void* const* d_in, const int* in_sizes, int n_in,
                              void* d_out, int out_size) {
    const float* x   = (const float*)d_in[0];
    const void*  ei  = d_in[1];
    const float* W1  = (const float*)d_in[2];
    const float* as1 = (const float*)d_in[3];
    const float* ad1 = (const float*)d_in[4];
    const float* b1  = (const float*)d_in[5];
    const float* W2  = (const float*)d_in[6];
    const float* as2 = (const float*)d_in[7];
    const float* ad2 = (const float*)d_in[8];
    const float* b2  = (const float*)d_in[9];

    int E = in_sizes[1] / 2;
    int HC1 = in_sizes[5];          // 256
    int HC2 = in_sizes[9];          // 160
    int F = in_sizes[2] / HC1;      // 128
    int N = in_sizes[0] / F;        // 50000
    int C1 = HC1 / 4;
    int C2 = HC2 / 4;

    // launch 0: detect + zero counts (merged)
    prep_kernel<<<ceil_div(N, 256) + 1, 256>>>((const unsigned int*)ei, E, N);

    // launches 1,2: column stats (standardization fused into GEMM-1 A-load)
    int nb = 200;
    int rowsPer = ceil_div(N, nb);
    colstats1<<<nb, FIN>>>(x, N, rowsPer);
    colstats2<<<1, FIN>>>(N, nb);

    // launch 3: GEMM layer 1 (positioned here so ncu's fixed launch-index
    // capture profiles it next round)
    {
        dim3 grid(ceil_div(N, 128), ceil_div(HC1, 64));
        gemm_tf32_kernel<<<grid, 256>>>(0, x, W1, N, F, HC1);
    }

    // CSR build (independent of GEMM; shared by both layers)
    csr_count<<<ceil_div(E, 256), 256>>>(ei, E);
    csr_scan<<<1, 1024>>>(N);
    csr_scatter<<<ceil_div(E + N, 256), 256>>>(ei, E, N);

    // ---- layer 1 attention + aggregation ----
    att_kernel<<<ceil_div(N * 4, 8), 256>>>(as1, ad1, N, C1);
    agg_kernel<<<ceil_div(N, 8), 256>>>(b1, nullptr, 0, N, HC1, C1, 1);

    // ---- layer 2 ----
    {
        dim3 grid(ceil_div(N, 128), ceil_div(HC2, 64));
        gemm_tf32_kernel<<<grid, 256>>>(1, nullptr, W2, N, HC1, HC2);
    }
    att_kernel<<<ceil_div(N * 4, 8), 256>>>(as2, ad2, N, C2);
    agg_kernel<<<ceil_div(N, 8), 256>>>(b2, (float*)d_out, 1, N, HC2, C2, 0);
}

// round 10
// speedup vs baseline: 1.6859x; 1.1164x over previous
#include <cuda_runtime.h>
#include <cuda_fp16.h>
#include <math.h>

// ---------------- problem capacity constants ----------------
#define MAXN 50000
#define MAXE 800000
#define MAXEL (MAXE + MAXN)   // edges + self loops
#define FIN 128
#define HC1MAX 256

#define PITCH_A 40   // halves; 80B rows, 16B-aligned, LDSM conflict-free
#define PITCH_B 72   // halves; 144B rows, 16B-aligned, LDSM conflict-free

// ---------------- device scratch (no allocations allowed) ----------------
__device__ float  g_h[MAXN * HC1MAX];        // GEMM output (h) fp32, reused per layer
__device__ __half g_h16[MAXN * HC1MAX];      // fp16 copy of h for agg gather
__device__ __half g_out1h[MAXN * HC1MAX];    // layer1 output (post relu), fp16
__device__ float  g_asrc[MAXN * 4];
__device__ float  g_adst[MAXN * 4];
__device__ int    g_counts[MAXN];
__device__ int    g_off[MAXN + 1];
__device__ int    g_cursor[MAXN];
__device__ int    g_col[MAXEL];
__device__ float  g_part[256 * 260];         // column-stat partials
__device__ float  g_mean[FIN];
__device__ float  g_istd[FIN];
__device__ int    g_is64;

static inline int ceil_div(int a, int b) { return (a + b - 1) / b; }

// ---------------- prep: edge-dtype detect + zero CSR counts (merged) ----------
__global__ void prep_kernel(const unsigned int* p, int E, int N) {
    int b = blockIdx.x;
    if (b == gridDim.x - 1) {
        __shared__ unsigned int acc;
        if (threadIdx.x == 0) acc = 0u;
        __syncthreads();
        int n = E < 1024 ? E : 1024;
        unsigned int v = 0;
        for (int i = threadIdx.x; i < n; i += blockDim.x) v |= p[2 * i + 1];
        atomicOr(&acc, v);
        __syncthreads();
        if (threadIdx.x == 0) g_is64 = (acc == 0u) ? 1 : 0;
    } else {
        int i = b * blockDim.x + threadIdx.x;
        if (i < N) g_counts[i] = 1;   // self loop
    }
}

__device__ __forceinline__ void get_edge(const void* ei, int E, int k, int& s, int& d) {
    if (g_is64) {
        const long long* p = (const long long*)ei;
        s = (int)p[k]; d = (int)p[E + k];
    } else {
        const int* p = (const int*)ei;
        s = p[k]; d = p[E + k];
    }
}

// ---------------- column stats (mean, std ddof=1) ----------------
__global__ void colstats1(const float* __restrict__ x, int N, int rowsPer) {
    int f = threadIdx.x;           // FIN threads
    int b = blockIdx.x;
    int r0 = b * rowsPer;
    int r1 = r0 + rowsPer; if (r1 > N) r1 = N;
    float s = 0.f, s2 = 0.f;
    for (int r = r0; r < r1; r++) {
        float v = x[(size_t)r * FIN + f];
        s += v; s2 += v * v;
    }
    g_part[b * 2 * FIN + f] = s;
    g_part[b * 2 * FIN + FIN + f] = s2;
}

__global__ void colstats2(int N, int nb) {
    int f = threadIdx.x;
    double s = 0.0, s2 = 0.0;
    for (int b = 0; b < nb; b++) {
        s  += (double)g_part[b * 2 * FIN + f];
        s2 += (double)g_part[b * 2 * FIN + FIN + f];
    }
    double mean = s / (double)N;
    double var = (s2 - s * s / (double)N) / (double)(N - 1);
    g_mean[f] = (float)mean;
    g_istd[f] = (float)(1.0 / sqrt(var));
}

// ---------------- CSR build (by dst, self-loops included) ----------------
__global__ void csr_count(const void* ei, int E) {
    int k = blockIdx.x * blockDim.x + threadIdx.x;
    if (k >= E) return;
    int s, d; get_edge(ei, E, k, s, d);
    atomicAdd(&g_counts[d], 1);
}

__global__ void csr_scan(int N) {
    __shared__ int sm[1024];
    int t = threadIdx.x;
    int chunk = (N + 1023) / 1024;
    int start = t * chunk;
    int end = start + chunk; if (end > N) end = N;
    int sum = 0;
    for (int i = start; i < end; i++) sum += g_counts[i];
    sm[t] = sum;
    __syncthreads();
    for (int o = 1; o < 1024; o <<= 1) {
        int v = (t >= o) ? sm[t - o] : 0;
        __syncthreads();
        sm[t] += v;
        __syncthreads();
    }
    int run = sm[t] - sum;   // exclusive
    for (int i = start; i < end; i++) {
        g_off[i] = run;
        g_cursor[i] = run;
        run += g_counts[i];
    }
    if (t == 1023) g_off[N] = sm[1023];
}

__global__ void csr_scatter(const void* ei, int E, int N) {
    int k = blockIdx.x * blockDim.x + threadIdx.x;
    if (k >= E + N) return;
    int s, d;
    if (k < E) get_edge(ei, E, k, s, d);
    else { s = k - E; d = s; }
    int pos = atomicAdd(&g_cursor[d], 1);
    g_col[pos] = s;
}

// ---------------- fp16 tensor-core GEMM (m16n8k16 + ldmatrix) ----------------
// C[N,M] = A[N,K] @ B[K,M].  BM=128, BN=64, BK=32, 256 threads (8 warps, 4x2).
// Warp tile 32x32 = 2x4 m16n8k16. A smem [m][k] pitch 40; B smem [k][n] pitch 72.
// asel==0: A = Aext fp32 with fused standardization; asel==1: A = g_out1h fp16.
// Epilogue writes fp32 g_h and fp16 g_h16.

__device__ __forceinline__ void mma_f16(float* c, const unsigned* a, const unsigned* b) {
    asm volatile(
        "mma.sync.aligned.m16n8k16.row.col.f32.f16.f16.f32 "
        "{%0,%1,%2,%3}, {%4,%5,%6,%7}, {%8,%9}, {%0,%1,%2,%3};\n"
        : "+f"(c[0]), "+f"(c[1]), "+f"(c[2]), "+f"(c[3])
        : "r"(a[0]), "r"(a[1]), "r"(a[2]), "r"(a[3]), "r"(b[0]), "r"(b[1]));
}

__device__ __forceinline__ unsigned pack_h2(float lo, float hi) {
    __half2 h = __floats2half2_rn(lo, hi);
    return *(unsigned*)&h;
}

__global__ __launch_bounds__(256)
void gemm_f16_kernel(int asel, const float* __restrict__ Aext,
                     const float* __restrict__ B, int N, int K, int M) {
    __shared__ __half As[128 * PITCH_A];
    __shared__ __half Bs[32 * PITCH_B];

    const int t = threadIdx.x;
    const int lane = t & 31;
    const int warp = t >> 5;
    const int groupID = lane >> 2;
    const int tig = lane & 3;
    const int warp_m = warp >> 1;   // 0..3
    const int warp_n = warp & 1;    // 0..1

    const int row0 = blockIdx.x * 128;
    const int col0 = blockIdx.y * 64;

    const int aRow = t >> 1;          // 0..127
    const int aC0  = (t & 1) * 16;    // 0 or 16
    const int bRow = t >> 3;          // 0..31
    const int bC0  = (t & 7) * 8;     // 0..56

    const int gRowA = row0 + aRow;
    const bool aOK = gRowA < N;
    const int gColB = col0 + bC0;
    const bool bOK = gColB < M;

    float acc[2][4][4];
#pragma unroll
    for (int i = 0; i < 2; i++)
#pragma unroll
        for (int j = 0; j < 4; j++)
#pragma unroll
            for (int c = 0; c < 4; c++) acc[i][j][c] = 0.f;

    const int T = K >> 5;
    uint4 aR0, aR1, bR;
    const uint4 z4 = make_uint4(0u, 0u, 0u, 0u);

    // ---- stage loaders (into registers) ----
    auto loadA = [&](int kb) {
        if (!aOK) { aR0 = z4; aR1 = z4; return; }
        if (asel) {
            const __half* p = g_out1h + (size_t)gRowA * K + kb + aC0;
            aR0 = *(const uint4*)p;
            aR1 = *(const uint4*)(p + 8);
        } else {
            const float* p = Aext + (size_t)gRowA * K + kb + aC0;
            unsigned h[8];
#pragma unroll
            for (int q = 0; q < 4; q++) {
                float4 v = *(const float4*)(p + q * 4);
                int c = kb + aC0 + q * 4;
                float4 mn = *(const float4*)(g_mean + c);
                float4 is = *(const float4*)(g_istd + c);
                v.x = (v.x - mn.x) * is.x; v.y = (v.y - mn.y) * is.y;
                v.z = (v.z - mn.z) * is.z; v.w = (v.w - mn.w) * is.w;
                h[q * 2 + 0] = pack_h2(v.x, v.y);
                h[q * 2 + 1] = pack_h2(v.z, v.w);
            }
            aR0 = make_uint4(h[0], h[1], h[2], h[3]);
            aR1 = make_uint4(h[4], h[5], h[6], h[7]);
        }
    };
    auto loadB = [&](int kb) {
        if (!bOK) { bR = z4; return; }
        const float* p = B + (size_t)(kb + bRow) * M + gColB;
        float4 v0 = *(const float4*)(p);
        float4 v1 = *(const float4*)(p + 4);
        bR = make_uint4(pack_h2(v0.x, v0.y), pack_h2(v0.z, v0.w),
                        pack_h2(v1.x, v1.y), pack_h2(v1.z, v1.w));
    };
    auto store_stage = [&]() {
        *(uint4*)&As[aRow * PITCH_A + aC0]     = aR0;
        *(uint4*)&As[aRow * PITCH_A + aC0 + 8] = aR1;
        *(uint4*)&Bs[bRow * PITCH_B + bC0]     = bR;
    };

    const unsigned sA = (unsigned)__cvta_generic_to_shared(As);
    const unsigned sB = (unsigned)__cvta_generic_to_shared(Bs);
    const int mbase = warp_m * 32;
    const int nbase = warp_n * 32;

    loadA(0); loadB(0);
    store_stage();
    __syncthreads();

    for (int tt = 0; tt < T; tt++) {
        if (tt + 1 < T) { loadA((tt + 1) * 32); loadB((tt + 1) * 32); }

#pragma unroll
        for (int k16 = 0; k16 < 32; k16 += 16) {
            unsigned a[2][4], b[2][4];
#pragma unroll
            for (int im = 0; im < 2; im++) {
                unsigned addr = sA + (unsigned)(((mbase + im * 16 + (lane & 15)) * PITCH_A
                                                + k16 + (lane >> 4) * 8) * 2);
                asm volatile("ldmatrix.sync.aligned.m8n8.x4.shared.b16 {%0,%1,%2,%3}, [%4];"
                             : "=r"(a[im][0]), "=r"(a[im][1]), "=r"(a[im][2]), "=r"(a[im][3])
                             : "r"(addr));
            }
#pragma unroll
            for (int jp = 0; jp < 2; jp++) {
                unsigned addr = sB + (unsigned)(((k16 + ((lane >> 3) & 1) * 8 + (lane & 7)) * PITCH_B
                                                + nbase + jp * 16 + (lane >> 4) * 8) * 2);
                asm volatile("ldmatrix.sync.aligned.m8n8.x4.trans.shared.b16 {%0,%1,%2,%3}, [%4];"
                             : "=r"(b[jp][0]), "=r"(b[jp][1]), "=r"(b[jp][2]), "=r"(b[jp][3])
                             : "r"(addr));
            }
#pragma unroll
            for (int im = 0; im < 2; im++)
#pragma unroll
                for (int in_ = 0; in_ < 4; in_++)
                    mma_f16(acc[im][in_], a[im], &b[in_ >> 1][(in_ & 1) * 2]);
        }

        if (tt + 1 < T) {
            __syncthreads();
            store_stage();
            __syncthreads();
        }
    }

    // ---- epilogue: fp32 + fp16 copies ----
#pragma unroll
    for (int im = 0; im < 2; im++) {
        int r_ = row0 + warp_m * 32 + im * 16 + groupID;
#pragma unroll
        for (int in_ = 0; in_ < 4; in_++) {
            int c_ = col0 + warp_n * 32 + in_ * 8 + tig * 2;
            if (c_ < M) {
                if (r_ < N) {
                    *(float2*)(g_h + (size_t)r_ * M + c_) =
                        make_float2(acc[im][in_][0], acc[im][in_][1]);
                    *(half2*)(g_h16 + (size_t)r_ * M + c_) =
                        __floats2half2_rn(acc[im][in_][0], acc[im][in_][1]);
                }
                if (r_ + 8 < N) {
                    *(float2*)(g_h + (size_t)(r_ + 8) * M + c_) =
                        make_float2(acc[im][in_][2], acc[im][in_][3]);
                    *(half2*)(g_h16 + (size_t)(r_ + 8) * M + c_) =
                        __floats2half2_rn(acc[im][in_][2], acc[im][in_][3]);
                }
            }
        }
    }
}

// ---------------- attention coefficients: a_src/a_dst [N,H] ----------------
__global__ void att_kernel(const float* __restrict__ att_s, const float* __restrict__ att_d,
                           int N, int C) {
    int warp = (blockIdx.x * blockDim.x + threadIdx.x) >> 5;
    int lane = threadIdx.x & 31;
    int total = N * 4;
    if (warp >= total) return;
    int n = warp >> 2, hh = warp & 3;
    const float* hp = g_h + (size_t)n * 4 * C + hh * C;
    float s1 = 0.f, s2 = 0.f;
    for (int c = lane; c < C; c += 32) {
        float v = hp[c];
        s1 += v * att_s[hh * C + c];
        s2 += v * att_d[hh * C + c];
    }
#pragma unroll
    for (int o = 16; o; o >>= 1) {
        s1 += __shfl_xor_sync(0xffffffffu, s1, o);
        s2 += __shfl_xor_sync(0xffffffffu, s2, o);
    }
    if (lane == 0) {
        g_asrc[n * 4 + hh] = s1;
        g_adst[n * 4 + hh] = s2;
    }
}

// ---------------- single-pass aggregation: warp per dst ----------------
// Chunked: lanes compute e for 32 edges in parallel, stash {src, e0..e3} in
// smem, then gather with broadcasts. Layer1 output written as fp16 (g_out1h),
// layer2 written fp32 to d_out.
__global__ __launch_bounds__(256)
void agg_kernel(const float* __restrict__ bias, float* __restrict__ out_ext,
                int use_ext, int N, int HC, int C, int do_relu) {
    __shared__ float sm_e[8][32][4];
    __shared__ int   sm_s[8][32];
    int w = threadIdx.x >> 5;
    int warp = (blockIdx.x * blockDim.x + threadIdx.x) >> 5;
    int lane = threadIdx.x & 31;
    if (warp >= N) return;
    int d = warp;
    int beg = g_off[d], end = g_off[d + 1];
    float4 ad = *(const float4*)(g_adst + d * 4);

    int j0 = lane * 8;                 // 8 halves per lane
    bool act = j0 < HC;                // HC=256: all lanes; HC=160: lanes 0..19
    int h0 = act ? (j0 / C) : 0;       // head for this lane's block (8 | C)
    const __half* __restrict__ hbase = g_h16 + j0;

    float acc[8];
#pragma unroll
    for (int q = 0; q < 8; q++) acc[q] = 0.f;
    float den0 = 0.f, den1 = 0.f, den2 = 0.f, den3 = 0.f;

    for (int i0 = beg; i0 < end; i0 += 32) {
        int i = i0 + lane;
        bool ea = i < end;
        int s = ea ? g_col[i] : 0;
        float4 as = *(const float4*)(g_asrc + s * 4);
        float e0 = as.x + ad.x; e0 = e0 > 0.f ? e0 : 0.2f * e0; e0 = __expf(e0);
        float e1 = as.y + ad.y; e1 = e1 > 0.f ? e1 : 0.2f * e1; e1 = __expf(e1);
        float e2 = as.z + ad.z; e2 = e2 > 0.f ? e2 : 0.2f * e2; e2 = __expf(e2);
        float e3 = as.w + ad.w; e3 = e3 > 0.f ? e3 : 0.2f * e3; e3 = __expf(e3);
        if (ea) { den0 += e0; den1 += e1; den2 += e2; den3 += e3; }
        sm_s[w][lane] = s;
        *(float4*)&sm_e[w][lane][0] = make_float4(e0, e1, e2, e3);
        __syncwarp();

        int cnt = end - i0; if (cnt > 32) cnt = 32;
        if (act) {
            for (int j = 0; j < cnt; j++) {
                int ss = sm_s[w][j];                    // uniform (broadcast LDS)
                float aa = sm_e[w][j][h0];              // 4-way LDS, conflict-free
                uint4 hv = *(const uint4*)(hbase + (size_t)ss * HC);
                float2 f0 = __half22float2(*(const half2*)&hv.x);
                float2 f1 = __half22float2(*(const half2*)&hv.y);
                float2 f2 = __half22float2(*(const half2*)&hv.z);
                float2 f3 = __half22float2(*(const half2*)&hv.w);
                acc[0] += aa * f0.x; acc[1] += aa * f0.y;
                acc[2] += aa * f1.x; acc[3] += aa * f1.y;
                acc[4] += aa * f2.x; acc[5] += aa * f2.y;
                acc[6] += aa * f3.x; acc[7] += aa * f3.y;
            }
        }
        __syncwarp();
    }

#pragma unroll
    for (int o = 16; o; o >>= 1) {
        den0 += __shfl_xor_sync(0xffffffffu, den0, o);
        den1 += __shfl_xor_sync(0xffffffffu, den1, o);
        den2 += __shfl_xor_sync(0xffffffffu, den2, o);
        den3 += __shfl_xor_sync(0xffffffffu, den3, o);
    }

    if (act) {
        float dd = h0 == 0 ? den0 : (h0 == 1 ? den1 : (h0 == 2 ? den2 : den3));
        float r = 1.f / dd;
        float4 b0 = *(const float4*)(bias + j0);
        float4 b1 = *(const float4*)(bias + j0 + 4);
        float o0[4], o1[4];
        o0[0] = acc[0] * r + b0.x; o0[1] = acc[1] * r + b0.y;
        o0[2] = acc[2] * r + b0.z; o0[3] = acc[3] * r + b0.w;
        o1[0] = acc[4] * r + b1.x; o1[1] = acc[5] * r + b1.y;
        o1[2] = acc[6] * r + b1.z; o1[3] = acc[7] * r + b1.w;
        if (do_relu) {
#pragma unroll
            for (int q = 0; q < 4; q++) {
                o0[q] = fmaxf(o0[q], 0.f);
                o1[q] = fmaxf(o1[q], 0.f);
            }
        }
        if (use_ext) {
            *(float4*)(out_ext + (size_t)d * HC + j0)     = make_float4(o0[0], o0[1], o0[2], o0[3]);
            *(float4*)(out_ext + (size_t)d * HC + j0 + 4) = make_float4(o1[0], o1[1], o1[2], o1[3]);
        } else {
            uint4 pk;
            pk.x = pack_h2(o0[0], o0[1]); pk.y = pack_h2(o0[2], o0[3]);
            pk.z = pack_h2(o1[0], o1[1]); pk.w = pack_h2(o1[2], o1[3]);
            *(uint4*)(g_out1h + (size_t)d * HC + j0) = pk;
        }
    }
}

// ---------------- launch ----------------
extern "C" void kernel_launch(void* const* d_in, const int* in_sizes, int n_in,
                              void* d_out, int out_size) {
    const float* x   = (const float*)d_in[0];
    const void*  ei  = d_in[1];
    const float* W1  = (const float*)d_in[2];
    const float* as1 = (const float*)d_in[3];
    const float* ad1 = (const float*)d_in[4];
    const float* b1  = (const float*)d_in[5];
    const float* W2  = (const float*)d_in[6];
    const float* as2 = (const float*)d_in[7];
    const float* ad2 = (const float*)d_in[8];
    const float* b2  = (const float*)d_in[9];

    int E = in_sizes[1] / 2;
    int HC1 = in_sizes[5];          // 256
    int HC2 = in_sizes[9];          // 160
    int F = in_sizes[2] / HC1;      // 128
    int N = in_sizes[0] / F;        // 50000
    int C1 = HC1 / 4;
    int C2 = HC2 / 4;

    // launch 0: detect + zero counts (merged)
    prep_kernel<<<ceil_div(N, 256) + 1, 256>>>((const unsigned int*)ei, E, N);

    // launches 1,2: column stats (standardization fused into GEMM-1 A-load)
    int nb = 200;
    int rowsPer = ceil_div(N, nb);
    colstats1<<<nb, FIN>>>(x, N, rowsPer);
    colstats2<<<1, FIN>>>(N, nb);

    // launch 3: GEMM layer 1 (kept at index 3 for ncu capture)
    {
        dim3 grid(ceil_div(N, 128), ceil_div(HC1, 64));
        gemm_f16_kernel<<<grid, 256>>>(0, x, W1, N, F, HC1);
    }

    // CSR build (independent of GEMM; shared by both layers)
    csr_count<<<ceil_div(E, 256), 256>>>(ei, E);
    csr_scan<<<1, 1024>>>(N);
    csr_scatter<<<ceil_div(E + N, 256), 256>>>(ei, E, N);

    // ---- layer 1 attention + aggregation ----
    att_kernel<<<ceil_div(N * 4, 8), 256>>>(as1, ad1, N, C1);
    agg_kernel<<<ceil_div(N, 8), 256>>>(b1, nullptr, 0, N, HC1, C1, 1);

    // ---- layer 2 ----
    {
        dim3 grid(ceil_div(N, 128), ceil_div(HC2, 64));
        gemm_f16_kernel<<<grid, 256>>>(1, nullptr, W2, N, HC1, HC2);
    }
    att_kernel<<<ceil_div(N * 4, 8), 256>>>(as2, ad2, N, C2);
    agg_kernel<<<ceil_div(N, 8), 256>>>(b2, (float*)d_out, 1, N, HC2, C2, 0);
}

// round 11
// speedup vs baseline: 2.0337x; 1.2063x over previous
#include <cuda_runtime.h>
#include <cuda_fp16.h>
#include <math.h>

// ---------------- problem capacity constants ----------------
#define MAXN 50000
#define MAXE 800000
#define MAXEL (MAXE + MAXN)   // edges + self loops
#define FIN 128
#define HC1MAX 256

#define PITCH_A 40   // halves; 80B rows, 16B-aligned, LDSM conflict-free
#define PITCH_B 72   // halves; 144B rows, 16B-aligned, LDSM conflict-free

// ---------------- device scratch (no allocations allowed) ----------------
__device__ __half g_h16[MAXN * HC1MAX];      // GEMM output (fp16), per layer
__device__ __half g_out1h[MAXN * HC1MAX];    // layer1 output (post relu), fp16
__device__ float  g_att[4 * MAXN * 4];       // [S1, D1, S2, D2] segments
__device__ __half g_w1h[HC1MAX * HC1MAX];    // W1 fp16
__device__ __half g_w2h[HC1MAX * HC1MAX];    // W2 fp16
__device__ int    g_counts[MAXN];
__device__ int    g_off[MAXN + 1];
__device__ int    g_cursor[MAXN];
__device__ int    g_col[MAXEL];
__device__ float  g_part[256 * 260];         // column-stat partials
__device__ float  g_mean[FIN];
__device__ float  g_istd[FIN];
__device__ int    g_is64;

static inline int ceil_div(int a, int b) { return (a + b - 1) / b; }

__device__ __forceinline__ unsigned pack_h2(float lo, float hi) {
    __half2 h = __floats2half2_rn(lo, hi);
    return *(unsigned*)&h;
}

// ---------------- prep: detect + counts init + att zero + weight cvt ---------
__global__ void prep_kernel(const unsigned int* p, const float* __restrict__ W1,
                            const float* __restrict__ W2, int E, int N,
                            int nW1, int nW2) {
    int b = blockIdx.x;
    if (b == gridDim.x - 1) {
        __shared__ unsigned int acc;
        if (threadIdx.x == 0) acc = 0u;
        __syncthreads();
        int n = E < 1024 ? E : 1024;
        unsigned int v = 0;
        for (int i = threadIdx.x; i < n; i += blockDim.x) v |= p[2 * i + 1];
        atomicOr(&acc, v);
        __syncthreads();
        if (threadIdx.x == 0) g_is64 = (acc == 0u) ? 1 : 0;
        return;
    }
    int idx = b * blockDim.x + threadIdx.x;
    if (idx < N) { g_counts[idx] = 1; return; }          // self loop
    idx -= N;
    if (idx < 4 * MAXN) {                                 // zero att accumulators
        ((float4*)g_att)[idx] = make_float4(0.f, 0.f, 0.f, 0.f);
        return;
    }
    idx -= 4 * MAXN;
    if (idx < nW1) { g_w1h[idx] = __float2half_rn(W1[idx]); return; }
    idx -= nW1;
    if (idx < nW2) { g_w2h[idx] = __float2half_rn(W2[idx]); return; }
}

__device__ __forceinline__ void get_edge(const void* ei, int E, int k, int& s, int& d) {
    if (g_is64) {
        const long long* p = (const long long*)ei;
        s = (int)p[k]; d = (int)p[E + k];
    } else {
        const int* p = (const int*)ei;
        s = p[k]; d = p[E + k];
    }
}

// ---------------- column stats (mean, std ddof=1) ----------------
__global__ void colstats1(const float* __restrict__ x, int N, int rowsPer) {
    int f = threadIdx.x;           // FIN threads
    int b = blockIdx.x;
    int r0 = b * rowsPer;
    int r1 = r0 + rowsPer; if (r1 > N) r1 = N;
    float s = 0.f, s2 = 0.f;
    for (int r = r0; r < r1; r++) {
        float v = x[(size_t)r * FIN + f];
        s += v; s2 += v * v;
    }
    g_part[b * 2 * FIN + f] = s;
    g_part[b * 2 * FIN + FIN + f] = s2;
}

__global__ void colstats2(int N, int nb) {
    int f = threadIdx.x;
    double s = 0.0, s2 = 0.0;
    for (int b = 0; b < nb; b++) {
        s  += (double)g_part[b * 2 * FIN + f];
        s2 += (double)g_part[b * 2 * FIN + FIN + f];
    }
    double mean = s / (double)N;
    double var = (s2 - s * s / (double)N) / (double)(N - 1);
    g_mean[f] = (float)mean;
    g_istd[f] = (float)(1.0 / sqrt(var));
}

// ---------------- CSR build (by dst, self-loops included) ----------------
__global__ void csr_count(const void* ei, int E) {
    int k = blockIdx.x * blockDim.x + threadIdx.x;
    if (k >= E) return;
    int s, d; get_edge(ei, E, k, s, d);
    atomicAdd(&g_counts[d], 1);
}

__global__ void csr_scan(int N) {
    __shared__ int sm[1024];
    int t = threadIdx.x;
    int chunk = (N + 1023) / 1024;
    int start = t * chunk;
    int end = start + chunk; if (end > N) end = N;
    int sum = 0;
    for (int i = start; i < end; i++) sum += g_counts[i];
    sm[t] = sum;
    __syncthreads();
    for (int o = 1; o < 1024; o <<= 1) {
        int v = (t >= o) ? sm[t - o] : 0;
        __syncthreads();
        sm[t] += v;
        __syncthreads();
    }
    int run = sm[t] - sum;   // exclusive
    for (int i = start; i < end; i++) {
        g_off[i] = run;
        g_cursor[i] = run;
        run += g_counts[i];
    }
    if (t == 1023) g_off[N] = sm[1023];
}

__global__ void csr_scatter(const void* ei, int E, int N) {
    int k = blockIdx.x * blockDim.x + threadIdx.x;
    if (k >= E + N) return;
    int s, d;
    if (k < E) get_edge(ei, E, k, s, d);
    else { s = k - E; d = s; }
    int pos = atomicAdd(&g_cursor[d], 1);
    g_col[pos] = s;
}

// ---------------- fp16 tensor-core GEMM (m16n8k16 + ldmatrix) ----------------
// C[N,M] = A[N,K] @ B[K,M].  BM=128, BN=64, BK=32, 256 threads (8 warps, 4x2).
// ASEL==0: A = Aext fp32 + fused standardization; ASEL==1: A = g_out1h fp16.
// B = g_w1h/g_w2h fp16 (pre-converted). Epilogue: fp16 g_h16 store + fused
// attention projections (a_src/a_dst) accumulated into g_att via atomics.

__device__ __forceinline__ void mma_f16(float* c, const unsigned* a, const unsigned* b) {
    asm volatile(
        "mma.sync.aligned.m16n8k16.row.col.f32.f16.f16.f32 "
        "{%0,%1,%2,%3}, {%4,%5,%6,%7}, {%8,%9}, {%0,%1,%2,%3};\n"
        : "+f"(c[0]), "+f"(c[1]), "+f"(c[2]), "+f"(c[3])
        : "r"(a[0]), "r"(a[1]), "r"(a[2]), "r"(a[3]), "r"(b[0]), "r"(b[1]));
}

template <int K, int M, int C, int ASEL>
__global__ __launch_bounds__(256)
void gemm_f16_kernel(const float* __restrict__ Aext,
                     const float* __restrict__ att_s,
                     const float* __restrict__ att_d, int N) {
    __shared__ __half As[128 * PITCH_A];
    __shared__ __half Bs[32 * PITCH_B];

    const int t = threadIdx.x;
    const int lane = t & 31;
    const int warp = t >> 5;
    const int groupID = lane >> 2;
    const int tig = lane & 3;
    const int warp_m = warp >> 1;   // 0..3
    const int warp_n = warp & 1;    // 0..1

    const int row0 = blockIdx.x * 128;
    const int col0 = blockIdx.y * 64;

    const int aRow = t >> 1;          // 0..127
    const int aC0  = (t & 1) * 16;    // 0 or 16
    const int bRow = t >> 3;          // 0..31
    const int bC0  = (t & 7) * 8;     // 0..56

    const int gRowA = row0 + aRow;
    const bool aOK = gRowA < N;
    const int gColB = col0 + bC0;

    float acc[2][4][4];
#pragma unroll
    for (int i = 0; i < 2; i++)
#pragma unroll
        for (int j = 0; j < 4; j++)
#pragma unroll
            for (int c = 0; c < 4; c++) acc[i][j][c] = 0.f;

    constexpr int T = K >> 5;
    uint4 aR0, aR1, bR;
    const uint4 z4 = make_uint4(0u, 0u, 0u, 0u);
    const __half* __restrict__ Wp = ASEL ? g_w2h : g_w1h;

    auto loadA = [&](int kb) {
        if (!aOK) { aR0 = z4; aR1 = z4; return; }
        if (ASEL) {
            const __half* p = g_out1h + (size_t)gRowA * K + kb + aC0;
            aR0 = *(const uint4*)p;
            aR1 = *(const uint4*)(p + 8);
        } else {
            const float* p = Aext + (size_t)gRowA * K + kb + aC0;
            unsigned h[8];
#pragma unroll
            for (int q = 0; q < 4; q++) {
                float4 v = *(const float4*)(p + q * 4);
                int c = kb + aC0 + q * 4;
                float4 mn = *(const float4*)(g_mean + c);
                float4 is = *(const float4*)(g_istd + c);
                v.x = (v.x - mn.x) * is.x; v.y = (v.y - mn.y) * is.y;
                v.z = (v.z - mn.z) * is.z; v.w = (v.w - mn.w) * is.w;
                h[q * 2 + 0] = pack_h2(v.x, v.y);
                h[q * 2 + 1] = pack_h2(v.z, v.w);
            }
            aR0 = make_uint4(h[0], h[1], h[2], h[3]);
            aR1 = make_uint4(h[4], h[5], h[6], h[7]);
        }
    };
    auto loadB = [&](int kb) {
        bR = *(const uint4*)(Wp + (size_t)(kb + bRow) * M + gColB);
    };
    auto store_stage = [&]() {
        *(uint4*)&As[aRow * PITCH_A + aC0]     = aR0;
        *(uint4*)&As[aRow * PITCH_A + aC0 + 8] = aR1;
        *(uint4*)&Bs[bRow * PITCH_B + bC0]     = bR;
    };

    const unsigned sA = (unsigned)__cvta_generic_to_shared(As);
    const unsigned sB = (unsigned)__cvta_generic_to_shared(Bs);
    const int mbase = warp_m * 32;
    const int nbase = warp_n * 32;

    loadA(0); loadB(0);
    store_stage();
    __syncthreads();

    for (int tt = 0; tt < T; tt++) {
        if (tt + 1 < T) { loadA((tt + 1) * 32); loadB((tt + 1) * 32); }

#pragma unroll
        for (int k16 = 0; k16 < 32; k16 += 16) {
            unsigned a[2][4], b[2][4];
#pragma unroll
            for (int im = 0; im < 2; im++) {
                unsigned addr = sA + (unsigned)(((mbase + im * 16 + (lane & 15)) * PITCH_A
                                                + k16 + (lane >> 4) * 8) * 2);
                asm volatile("ldmatrix.sync.aligned.m8n8.x4.shared.b16 {%0,%1,%2,%3}, [%4];"
                             : "=r"(a[im][0]), "=r"(a[im][1]), "=r"(a[im][2]), "=r"(a[im][3])
                             : "r"(addr));
            }
#pragma unroll
            for (int jp = 0; jp < 2; jp++) {
                unsigned addr = sB + (unsigned)(((k16 + ((lane >> 3) & 1) * 8 + (lane & 7)) * PITCH_B
                                                + nbase + jp * 16 + (lane >> 4) * 8) * 2);
                asm volatile("ldmatrix.sync.aligned.m8n8.x4.trans.shared.b16 {%0,%1,%2,%3}, [%4];"
                             : "=r"(b[jp][0]), "=r"(b[jp][1]), "=r"(b[jp][2]), "=r"(b[jp][3])
                             : "r"(addr));
            }
#pragma unroll
            for (int im = 0; im < 2; im++)
#pragma unroll
                for (int in_ = 0; in_ < 4; in_++)
                    mma_f16(acc[im][in_], a[im], &b[in_ >> 1][(in_ & 1) * 2]);
        }

        if (tt + 1 < T) {
            __syncthreads();
            store_stage();
            __syncthreads();
        }
    }

    // ---- epilogue: fp16 h store ----
#pragma unroll
    for (int im = 0; im < 2; im++) {
        int r_ = row0 + warp_m * 32 + im * 16 + groupID;
#pragma unroll
        for (int in_ = 0; in_ < 4; in_++) {
            int c_ = col0 + warp_n * 32 + in_ * 8 + tig * 2;
            if (c_ < M) {
                if (r_ < N)
                    *(half2*)(g_h16 + (size_t)r_ * M + c_) =
                        __floats2half2_rn(acc[im][in_][0], acc[im][in_][1]);
                if (r_ + 8 < N)
                    *(half2*)(g_h16 + (size_t)(r_ + 8) * M + c_) =
                        __floats2half2_rn(acc[im][in_][2], acc[im][in_][3]);
            }
        }
    }

    // ---- epilogue: fused attention projections ----
    // a_src[r][h] += sum_{c in head h} acc[r][c] * att_s_flat[c]  (att flat [H*C])
    float* __restrict__ attS = g_att + (2 * ASEL) * (MAXN * 4);
    float* __restrict__ attD = g_att + (2 * ASEL + 1) * (MAXN * 4);
    const int w0 = col0 + warp_n * 32;
    const int hlo = w0 / C;
    const int whi = (w0 + 31 < M - 1) ? (w0 + 31) : (M - 1);
    const int hhi = whi / C;            // warp-uniform; at most hlo+1

#pragma unroll
    for (int im = 0; im < 2; im++) {
#pragma unroll
        for (int hf = 0; hf < 2; hf++) {
            int r_ = row0 + warp_m * 32 + im * 16 + groupID + hf * 8;
            float ps0 = 0.f, ps1 = 0.f, pd0 = 0.f, pd1 = 0.f;
#pragma unroll
            for (int in_ = 0; in_ < 4; in_++) {
                int c = w0 + in_ * 8 + tig * 2;
                if (c < M) {
                    float a0 = acc[im][in_][hf * 2 + 0];
                    float a1 = acc[im][in_][hf * 2 + 1];
                    float sv = a0 * att_s[c] + a1 * att_s[c + 1];
                    float dv = a0 * att_d[c] + a1 * att_d[c + 1];
                    if (c / C != hlo) { ps1 += sv; pd1 += dv; }
                    else              { ps0 += sv; pd0 += dv; }
                }
            }
            ps0 += __shfl_xor_sync(0xffffffffu, ps0, 1);
            ps0 += __shfl_xor_sync(0xffffffffu, ps0, 2);
            pd0 += __shfl_xor_sync(0xffffffffu, pd0, 1);
            pd0 += __shfl_xor_sync(0xffffffffu, pd0, 2);
            if (tig == 0 && r_ < N) {
                atomicAdd(&attS[r_ * 4 + hlo], ps0);
                atomicAdd(&attD[r_ * 4 + hlo], pd0);
            }
            if (hhi > hlo) {
                ps1 += __shfl_xor_sync(0xffffffffu, ps1, 1);
                ps1 += __shfl_xor_sync(0xffffffffu, ps1, 2);
                pd1 += __shfl_xor_sync(0xffffffffu, pd1, 1);
                pd1 += __shfl_xor_sync(0xffffffffu, pd1, 2);
                if (tig == 0 && r_ < N) {
                    atomicAdd(&attS[r_ * 4 + hhi], ps1);
                    atomicAdd(&attD[r_ * 4 + hhi], pd1);
                }
            }
        }
    }
}

// ---------------- single-pass aggregation: warp per dst ----------------
// Chunked: lanes compute e for 32 edges in parallel, stash {src, e0..e3} in
// smem, then gather with broadcasts. Layer1 output -> g_out1h fp16 (+relu);
// layer2 -> d_out fp32.
__global__ __launch_bounds__(256)
void agg_kernel(const float* __restrict__ bias, float* __restrict__ out_ext,
                int use_ext, int N, int HC, int C, int do_relu, int layer) {
    __shared__ float sm_e[8][32][4];
    __shared__ int   sm_s[8][32];
    const float* __restrict__ attS = g_att + (2 * layer) * (MAXN * 4);
    const float* __restrict__ attD = g_att + (2 * layer + 1) * (MAXN * 4);
    int w = threadIdx.x >> 5;
    int warp = (blockIdx.x * blockDim.x + threadIdx.x) >> 5;
    int lane = threadIdx.x & 31;
    if (warp >= N) return;
    int d = warp;
    int beg = g_off[d], end = g_off[d + 1];
    float4 ad = *(const float4*)(attD + d * 4);

    int j0 = lane * 8;                 // 8 halves per lane
    bool act = j0 < HC;                // HC=256: all lanes; HC=160: lanes 0..19
    int h0 = act ? (j0 / C) : 0;       // head for this lane's block (8 | C)
    const __half* __restrict__ hbase = g_h16 + j0;

    float acc[8];
#pragma unroll
    for (int q = 0; q < 8; q++) acc[q] = 0.f;
    float den0 = 0.f, den1 = 0.f, den2 = 0.f, den3 = 0.f;

    for (int i0 = beg; i0 < end; i0 += 32) {
        int i = i0 + lane;
        bool ea = i < end;
        int s = ea ? g_col[i] : 0;
        float4 as = *(const float4*)(attS + s * 4);
        float e0 = as.x + ad.x; e0 = e0 > 0.f ? e0 : 0.2f * e0; e0 = __expf(e0);
        float e1 = as.y + ad.y; e1 = e1 > 0.f ? e1 : 0.2f * e1; e1 = __expf(e1);
        float e2 = as.z + ad.z; e2 = e2 > 0.f ? e2 : 0.2f * e2; e2 = __expf(e2);
        float e3 = as.w + ad.w; e3 = e3 > 0.f ? e3 : 0.2f * e3; e3 = __expf(e3);
        if (ea) { den0 += e0; den1 += e1; den2 += e2; den3 += e3; }
        sm_s[w][lane] = s;
        *(float4*)&sm_e[w][lane][0] = make_float4(e0, e1, e2, e3);
        __syncwarp();

        int cnt = end - i0; if (cnt > 32) cnt = 32;
        if (act) {
            for (int j = 0; j < cnt; j++) {
                int ss = sm_s[w][j];                    // uniform (broadcast LDS)
                float aa = sm_e[w][j][h0];              // 4-way LDS, conflict-free
                uint4 hv = *(const uint4*)(hbase + (size_t)ss * HC);
                float2 f0 = __half22float2(*(const half2*)&hv.x);
                float2 f1 = __half22float2(*(const half2*)&hv.y);
                float2 f2 = __half22float2(*(const half2*)&hv.z);
                float2 f3 = __half22float2(*(const half2*)&hv.w);
                acc[0] += aa * f0.x; acc[1] += aa * f0.y;
                acc[2] += aa * f1.x; acc[3] += aa * f1.y;
                acc[4] += aa * f2.x; acc[5] += aa * f2.y;
                acc[6] += aa * f3.x; acc[7] += aa * f3.y;
            }
        }
        __syncwarp();
    }

#pragma unroll
    for (int o = 16; o; o >>= 1) {
        den0 += __shfl_xor_sync(0xffffffffu, den0, o);
        den1 += __shfl_xor_sync(0xffffffffu, den1, o);
        den2 += __shfl_xor_sync(0xffffffffu, den2, o);
        den3 += __shfl_xor_sync(0xffffffffu, den3, o);
    }

    if (act) {
        float dd = h0 == 0 ? den0 : (h0 == 1 ? den1 : (h0 == 2 ? den2 : den3));
        float r = 1.f / dd;
        float4 b0 = *(const float4*)(bias + j0);
        float4 b1 = *(const float4*)(bias + j0 + 4);
        float o0[4], o1[4];
        o0[0] = acc[0] * r + b0.x; o0[1] = acc[1] * r + b0.y;
        o0[2] = acc[2] * r + b0.z; o0[3] = acc[3] * r + b0.w;
        o1[0] = acc[4] * r + b1.x; o1[1] = acc[5] * r + b1.y;
        o1[2] = acc[6] * r + b1.z; o1[3] = acc[7] * r + b1.w;
        if (do_relu) {
#pragma unroll
            for (int q = 0; q < 4; q++) {
                o0[q] = fmaxf(o0[q], 0.f);
                o1[q] = fmaxf(o1[q], 0.f);
            }
        }
        if (use_ext) {
            *(float4*)(out_ext + (size_t)d * HC + j0)     = make_float4(o0[0], o0[1], o0[2], o0[3]);
            *(float4*)(out_ext + (size_t)d * HC + j0 + 4) = make_float4(o1[0], o1[1], o1[2], o1[3]);
        } else {
            uint4 pk;
            pk.x = pack_h2(o0[0], o0[1]); pk.y = pack_h2(o0[2], o0[3]);
            pk.z = pack_h2(o1[0], o1[1]); pk.w = pack_h2(o1[2], o1[3]);
            *(uint4*)(g_out1h + (size_t)d * HC + j0) = pk;
        }
    }
}

// ---------------- launch ----------------
extern "C" void kernel_launch(void* const* d_in, const int* in_sizes, int n_in,
                              void* d_out, int out_size) {
    const float* x   = (const float*)d_in[0];
    const void*  ei  = d_in[1];
    const float* W1  = (const float*)d_in[2];
    const float* as1 = (const float*)d_in[3];
    const float* ad1 = (const float*)d_in[4];
    const float* b1  = (const float*)d_in[5];
    const float* W2  = (const float*)d_in[6];
    const float* as2 = (const float*)d_in[7];
    const float* ad2 = (const float*)d_in[8];
    const float* b2  = (const float*)d_in[9];

    int E = in_sizes[1] / 2;
    int HC1 = in_sizes[5];          // 256
    int HC2 = in_sizes[9];          // 160
    int F = in_sizes[2] / HC1;      // 128
    int N = in_sizes[0] / F;        // 50000
    int C1 = HC1 / 4;               // 64
    int C2 = HC2 / 4;               // 40
    int nW1 = in_sizes[2];
    int nW2 = in_sizes[6];

    // launch 0: detect + counts init + att zero + weight fp16 conversion
    {
        int work = N + 4 * MAXN + nW1 + nW2;
        prep_kernel<<<ceil_div(work, 256) + 1, 256>>>(
            (const unsigned int*)ei, W1, W2, E, N, nW1, nW2);
    }

    // launches 1,2: column stats (standardization fused into GEMM-1 A-load)
    int nb = 200;
    int rowsPer = ceil_div(N, nb);
    colstats1<<<nb, FIN>>>(x, N, rowsPer);
    colstats2<<<1, FIN>>>(N, nb);

    // launch 3: GEMM layer 1 (kept at index 3 for ncu capture)
    {
        dim3 grid(ceil_div(N, 128), ceil_div(HC1, 64));
        gemm_f16_kernel<128, 256, 64, 0><<<grid, 256>>>(x, as1, ad1, N);
    }

    // CSR build (independent of GEMM; shared by both layers)
    csr_count<<<ceil_div(E, 256), 256>>>(ei, E);
    csr_scan<<<1, 1024>>>(N);
    csr_scatter<<<ceil_div(E + N, 256), 256>>>(ei, E, N);

    // ---- layer 1 aggregation ----
    agg_kernel<<<ceil_div(N, 8), 256>>>(b1, nullptr, 0, N, HC1, C1, 1, 0);

    // ---- layer 2 ----
    {
        dim3 grid(ceil_div(N, 128), ceil_div(HC2, 64));
        gemm_f16_kernel<256, 160, 40, 1><<<grid, 256>>>(nullptr, as2, ad2, N);
    }
    agg_kernel<<<ceil_div(N, 8), 256>>>(b2, (float*)d_out, 1, N, HC2, C2, 0, 1);
}

// round 12
// speedup vs baseline: 2.1672x; 1.0656x over previous
#include <cuda_runtime.h>
#include <cuda_fp16.h>
#include <math.h>

// ---------------- problem capacity constants ----------------
#define MAXN 50000
#define MAXE 800000
#define MAXEL (MAXE + MAXN)   // edges + self loops
#define FIN 128
#define HC1MAX 256

#define PITCH_A 40   // halves; 80B rows, 16B-aligned, LDSM conflict-free
#define PITCH_B 72   // halves; 144B rows, 16B-aligned, LDSM conflict-free
#define ABYTES (128 * PITCH_A * 2)
#define BBYTES (32 * PITCH_B * 2)

// ---------------- device scratch (no allocations allowed) ----------------
__device__ __half g_xh[(MAXN + 128) * FIN];      // standardized x, fp16 (+pad rows)
__device__ __half g_h16[MAXN * HC1MAX];          // GEMM output (fp16), per layer
__device__ __half g_out1h[(MAXN + 128) * HC1MAX];// layer1 output (post relu), fp16 (+pad)
__device__ float  g_att[4 * MAXN * 4];           // [S1, D1, S2, D2] segments
__device__ __half g_w1h[HC1MAX * HC1MAX];        // W1 fp16
__device__ __half g_w2h[HC1MAX * HC1MAX];        // W2 fp16
__device__ int    g_counts[MAXN];
__device__ int    g_off[MAXN + 1];
__device__ int    g_cursor[MAXN];
__device__ int    g_col[MAXEL];
__device__ float  g_part[256 * 260];             // column-stat partials
__device__ float  g_mean[FIN];
__device__ float  g_istd[FIN];
__device__ int    g_is64;

static inline int ceil_div(int a, int b) { return (a + b - 1) / b; }

__device__ __forceinline__ unsigned pack_h2(float lo, float hi) {
    __half2 h = __floats2half2_rn(lo, hi);
    return *(unsigned*)&h;
}

__device__ __forceinline__ void cp16(unsigned smem_addr, const void* gptr) {
    asm volatile("cp.async.ca.shared.global [%0], [%1], 16;"
                 :: "r"(smem_addr), "l"(gptr));
}

// ---------------- column stats (mean, std ddof=1) ----------------
__global__ void colstats1(const float* __restrict__ x, int N, int rowsPer) {
    int f = threadIdx.x;           // FIN threads
    int b = blockIdx.x;
    int r0 = b * rowsPer;
    int r1 = r0 + rowsPer; if (r1 > N) r1 = N;
    float s = 0.f, s2 = 0.f;
    for (int r = r0; r < r1; r++) {
        float v = x[(size_t)r * FIN + f];
        s += v; s2 += v * v;
    }
    g_part[b * 2 * FIN + f] = s;
    g_part[b * 2 * FIN + FIN + f] = s2;
}

__global__ void colstats2(int N, int nb) {
    int f = threadIdx.x;
    double s = 0.0, s2 = 0.0;
    for (int b = 0; b < nb; b++) {
        s  += (double)g_part[b * 2 * FIN + f];
        s2 += (double)g_part[b * 2 * FIN + FIN + f];
    }
    double mean = s / (double)N;
    double var = (s2 - s * s / (double)N) / (double)(N - 1);
    g_mean[f] = (float)mean;
    g_istd[f] = (float)(1.0 / sqrt(var));
}

// ---------------- fin16: standardize x -> fp16, weight cvt, att zero --------
__global__ void fin16_kernel(const float* __restrict__ x,
                             const float* __restrict__ W1,
                             const float* __restrict__ W2,
                             int N, int nW1, int nW2) {
    int idx = blockIdx.x * blockDim.x + threadIdx.x;
    int nStd = N * (FIN / 8);
    if (idx < nStd) {
        int f8 = (idx & (FIN / 8 - 1)) * 8;
        const float4* xp = (const float4*)x + (size_t)idx * 2;
        float4 v0 = xp[0], v1 = xp[1];
        float4 mn0 = *(const float4*)(g_mean + f8);
        float4 is0 = *(const float4*)(g_istd + f8);
        float4 mn1 = *(const float4*)(g_mean + f8 + 4);
        float4 is1 = *(const float4*)(g_istd + f8 + 4);
        uint4 o;
        o.x = pack_h2((v0.x - mn0.x) * is0.x, (v0.y - mn0.y) * is0.y);
        o.y = pack_h2((v0.z - mn0.z) * is0.z, (v0.w - mn0.w) * is0.w);
        o.z = pack_h2((v1.x - mn1.x) * is1.x, (v1.y - mn1.y) * is1.y);
        o.w = pack_h2((v1.z - mn1.z) * is1.z, (v1.w - mn1.w) * is1.w);
        *((uint4*)g_xh + idx) = o;
        return;
    }
    idx -= nStd;
    if (idx < 4 * MAXN) {                                 // zero att accumulators
        ((float4*)g_att)[idx] = make_float4(0.f, 0.f, 0.f, 0.f);
        return;
    }
    idx -= 4 * MAXN;
    if (idx < nW1) { g_w1h[idx] = __float2half_rn(W1[idx]); return; }
    idx -= nW1;
    if (idx < nW2) { g_w2h[idx] = __float2half_rn(W2[idx]); return; }
}

// ---------------- prep: edge-dtype detect + counts init ----------------
__global__ void prep_kernel(const unsigned int* p, int E, int N) {
    int b = blockIdx.x;
    if (b == gridDim.x - 1) {
        __shared__ unsigned int acc;
        if (threadIdx.x == 0) acc = 0u;
        __syncthreads();
        int n = E < 1024 ? E : 1024;
        unsigned int v = 0;
        for (int i = threadIdx.x; i < n; i += blockDim.x) v |= p[2 * i + 1];
        atomicOr(&acc, v);
        __syncthreads();
        if (threadIdx.x == 0) g_is64 = (acc == 0u) ? 1 : 0;
        return;
    }
    int i = b * blockDim.x + threadIdx.x;
    if (i < N) g_counts[i] = 1;   // self loop
}

__device__ __forceinline__ void get_edge(const void* ei, int E, int k, int& s, int& d) {
    if (g_is64) {
        const long long* p = (const long long*)ei;
        s = (int)p[k]; d = (int)p[E + k];
    } else {
        const int* p = (const int*)ei;
        s = p[k]; d = p[E + k];
    }
}

// ---------------- CSR build (by dst, self-loops included) ----------------
__global__ void csr_count(const void* ei, int E) {
    int k = blockIdx.x * blockDim.x + threadIdx.x;
    if (k >= E) return;
    int s, d; get_edge(ei, E, k, s, d);
    atomicAdd(&g_counts[d], 1);
}

__global__ void csr_scan(int N) {
    __shared__ int sm[1024];
    int t = threadIdx.x;
    int chunk = (N + 1023) / 1024;
    int start = t * chunk;
    int end = start + chunk; if (end > N) end = N;
    int sum = 0;
    for (int i = start; i < end; i++) sum += g_counts[i];
    sm[t] = sum;
    __syncthreads();
    for (int o = 1; o < 1024; o <<= 1) {
        int v = (t >= o) ? sm[t - o] : 0;
        __syncthreads();
        sm[t] += v;
        __syncthreads();
    }
    int run = sm[t] - sum;   // exclusive
    for (int i = start; i < end; i++) {
        g_off[i] = run;
        g_cursor[i] = run;
        run += g_counts[i];
    }
    if (t == 1023) g_off[N] = sm[1023];
}

__global__ void csr_scatter(const void* ei, int E, int N) {
    int k = blockIdx.x * blockDim.x + threadIdx.x;
    if (k >= E + N) return;
    int s, d;
    if (k < E) get_edge(ei, E, k, s, d);
    else { s = k - E; d = s; }
    int pos = atomicAdd(&g_cursor[d], 1);
    g_col[pos] = s;
}

// ---------------- fp16 tensor-core GEMM (cp.async 2-stage + ldmatrix) --------
// C[N,M] = A[N,K] @ B[K,M].  BM=128, BN=64, BK=32, 256 threads (8 warps, 4x2).
// ASEL==0: A = g_xh; ASEL==1: A = g_out1h. B = g_w1h/g_w2h. All fp16 in gmem.
// Epilogue: fp16 g_h16 store + fused attention projections into g_att.

__device__ __forceinline__ void mma_f16(float* c, const unsigned* a, const unsigned* b) {
    asm volatile(
        "mma.sync.aligned.m16n8k16.row.col.f32.f16.f16.f32 "
        "{%0,%1,%2,%3}, {%4,%5,%6,%7}, {%8,%9}, {%0,%1,%2,%3};\n"
        : "+f"(c[0]), "+f"(c[1]), "+f"(c[2]), "+f"(c[3])
        : "r"(a[0]), "r"(a[1]), "r"(a[2]), "r"(a[3]), "r"(b[0]), "r"(b[1]));
}

template <int K, int M, int C, int ASEL>
__global__ __launch_bounds__(256, 4)
void gemm_f16_kernel(const float* __restrict__ att_s,
                     const float* __restrict__ att_d, int N) {
    __shared__ __half As[2][128 * PITCH_A];
    __shared__ __half Bs[2][32 * PITCH_B];

    const int t = threadIdx.x;
    const int lane = t & 31;
    const int warp = t >> 5;
    const int groupID = lane >> 2;
    const int tig = lane & 3;
    const int warp_m = warp >> 1;   // 0..3
    const int warp_n = warp & 1;    // 0..1

    const int row0 = blockIdx.x * 128;
    const int col0 = blockIdx.y * 64;

    const int aRow = t >> 1;          // 0..127
    const int aC0  = (t & 1) * 16;    // 0 or 16 (halves)
    const int bRow = t >> 3;          // 0..31
    const int bC0  = (t & 7) * 8;     // 0..56 (halves)

    const int gRowA = row0 + aRow;    // may exceed N; g_xh/g_out1h padded
    const int gColB = col0 + bC0;
    const bool bOK = gColB < M;

    const __half* __restrict__ Ag = ASEL ? g_out1h : g_xh;
    const __half* __restrict__ Wp = ASEL ? g_w2h : g_w1h;

    float acc[2][4][4];
#pragma unroll
    for (int i = 0; i < 2; i++)
#pragma unroll
        for (int j = 0; j < 4; j++)
#pragma unroll
            for (int c = 0; c < 4; c++) acc[i][j][c] = 0.f;

    constexpr int T = K >> 5;

    const unsigned sA = (unsigned)__cvta_generic_to_shared(&As[0][0]);
    const unsigned sB = (unsigned)__cvta_generic_to_shared(&Bs[0][0]);
    const unsigned aDst = sA + (unsigned)((aRow * PITCH_A + aC0) * 2);
    const unsigned bDst = sB + (unsigned)((bRow * PITCH_B + bC0) * 2);

    auto stage = [&](int kb, int buf) {
        const __half* ap = Ag + (size_t)gRowA * K + kb + aC0;
        cp16(aDst + buf * ABYTES, ap);
        cp16(aDst + buf * ABYTES + 16, ap + 8);
        if (bOK) {
            const __half* bp = Wp + (size_t)(kb + bRow) * M + gColB;
            cp16(bDst + buf * BBYTES, bp);
        }
    };

    stage(0, 0);
    asm volatile("cp.async.commit_group;");

    const int mbase = warp_m * 32;
    const int nbase = warp_n * 32;

    for (int tt = 0; tt < T; tt++) {
        const int cur = tt & 1;
        if (tt + 1 < T) {
            stage((tt + 1) * 32, cur ^ 1);
            asm volatile("cp.async.commit_group;");
            asm volatile("cp.async.wait_group 1;");
        } else {
            asm volatile("cp.async.wait_group 0;");
        }
        __syncthreads();

        const unsigned aB = sA + (unsigned)(cur * ABYTES);
        const unsigned bB = sB + (unsigned)(cur * BBYTES);
#pragma unroll
        for (int k16 = 0; k16 < 32; k16 += 16) {
            unsigned a[2][4], b[2][4];
#pragma unroll
            for (int im = 0; im < 2; im++) {
                unsigned addr = aB + (unsigned)(((mbase + im * 16 + (lane & 15)) * PITCH_A
                                                + k16 + (lane >> 4) * 8) * 2);
                asm volatile("ldmatrix.sync.aligned.m8n8.x4.shared.b16 {%0,%1,%2,%3}, [%4];"
                             : "=r"(a[im][0]), "=r"(a[im][1]), "=r"(a[im][2]), "=r"(a[im][3])
                             : "r"(addr));
            }
#pragma unroll
            for (int jp = 0; jp < 2; jp++) {
                unsigned addr = bB + (unsigned)(((k16 + ((lane >> 3) & 1) * 8 + (lane & 7)) * PITCH_B
                                                + nbase + jp * 16 + (lane >> 4) * 8) * 2);
                asm volatile("ldmatrix.sync.aligned.m8n8.x4.trans.shared.b16 {%0,%1,%2,%3}, [%4];"
                             : "=r"(b[jp][0]), "=r"(b[jp][1]), "=r"(b[jp][2]), "=r"(b[jp][3])
                             : "r"(addr));
            }
#pragma unroll
            for (int im = 0; im < 2; im++)
#pragma unroll
                for (int in_ = 0; in_ < 4; in_++)
                    mma_f16(acc[im][in_], a[im], &b[in_ >> 1][(in_ & 1) * 2]);
        }
        __syncthreads();
    }

    // ---- epilogue: fp16 h store ----
#pragma unroll
    for (int im = 0; im < 2; im++) {
        int r_ = row0 + warp_m * 32 + im * 16 + groupID;
#pragma unroll
        for (int in_ = 0; in_ < 4; in_++) {
            int c_ = col0 + warp_n * 32 + in_ * 8 + tig * 2;
            if (c_ < M) {
                if (r_ < N)
                    *(half2*)(g_h16 + (size_t)r_ * M + c_) =
                        __floats2half2_rn(acc[im][in_][0], acc[im][in_][1]);
                if (r_ + 8 < N)
                    *(half2*)(g_h16 + (size_t)(r_ + 8) * M + c_) =
                        __floats2half2_rn(acc[im][in_][2], acc[im][in_][3]);
            }
        }
    }

    // ---- epilogue: fused attention projections ----
    float* __restrict__ attS = g_att + (2 * ASEL) * (MAXN * 4);
    float* __restrict__ attD = g_att + (2 * ASEL + 1) * (MAXN * 4);
    const int w0 = col0 + warp_n * 32;
    if (w0 < M) {
        const int hlo = w0 / C;
        const int whi = (w0 + 31 < M - 1) ? (w0 + 31) : (M - 1);
        const int hhi = whi / C;            // warp-uniform; at most hlo+1

#pragma unroll
        for (int im = 0; im < 2; im++) {
#pragma unroll
            for (int hf = 0; hf < 2; hf++) {
                int r_ = row0 + warp_m * 32 + im * 16 + groupID + hf * 8;
                float ps0 = 0.f, ps1 = 0.f, pd0 = 0.f, pd1 = 0.f;
#pragma unroll
                for (int in_ = 0; in_ < 4; in_++) {
                    int c = w0 + in_ * 8 + tig * 2;
                    if (c < M) {
                        float a0 = acc[im][in_][hf * 2 + 0];
                        float a1 = acc[im][in_][hf * 2 + 1];
                        float sv = a0 * att_s[c] + a1 * att_s[c + 1];
                        float dv = a0 * att_d[c] + a1 * att_d[c + 1];
                        if (c / C != hlo) { ps1 += sv; pd1 += dv; }
                        else              { ps0 += sv; pd0 += dv; }
                    }
                }
                ps0 += __shfl_xor_sync(0xffffffffu, ps0, 1);
                ps0 += __shfl_xor_sync(0xffffffffu, ps0, 2);
                pd0 += __shfl_xor_sync(0xffffffffu, pd0, 1);
                pd0 += __shfl_xor_sync(0xffffffffu, pd0, 2);
                if (tig == 0 && r_ < N) {
                    atomicAdd(&attS[r_ * 4 + hlo], ps0);
                    atomicAdd(&attD[r_ * 4 + hlo], pd0);
                }
                if (hhi > hlo) {
                    ps1 += __shfl_xor_sync(0xffffffffu, ps1, 1);
                    ps1 += __shfl_xor_sync(0xffffffffu, ps1, 2);
                    pd1 += __shfl_xor_sync(0xffffffffu, pd1, 1);
                    pd1 += __shfl_xor_sync(0xffffffffu, pd1, 2);
                    if (tig == 0 && r_ < N) {
                        atomicAdd(&attS[r_ * 4 + hhi], ps1);
                        atomicAdd(&attD[r_ * 4 + hhi], pd1);
                    }
                }
            }
        }
    }
}

// ---------------- single-pass aggregation: warp per dst ----------------
__global__ __launch_bounds__(256)
void agg_kernel(const float* __restrict__ bias, float* __restrict__ out_ext,
                int use_ext, int N, int HC, int C, int do_relu, int layer) {
    __shared__ float sm_e[8][32][4];
    __shared__ int   sm_s[8][32];
    const float* __restrict__ attS = g_att + (2 * layer) * (MAXN * 4);
    const float* __restrict__ attD = g_att + (2 * layer + 1) * (MAXN * 4);
    int w = threadIdx.x >> 5;
    int warp = (blockIdx.x * blockDim.x + threadIdx.x) >> 5;
    int lane = threadIdx.x & 31;
    if (warp >= N) return;
    int d = warp;
    int beg = g_off[d], end = g_off[d + 1];
    float4 ad = *(const float4*)(attD + d * 4);

    int j0 = lane * 8;                 // 8 halves per lane
    bool act = j0 < HC;                // HC=256: all lanes; HC=160: lanes 0..19
    int h0 = act ? (j0 / C) : 0;       // head for this lane's block (8 | C)
    const __half* __restrict__ hbase = g_h16 + j0;

    float acc[8];
#pragma unroll
    for (int q = 0; q < 8; q++) acc[q] = 0.f;
    float den0 = 0.f, den1 = 0.f, den2 = 0.f, den3 = 0.f;

    for (int i0 = beg; i0 < end; i0 += 32) {
        int i = i0 + lane;
        bool ea = i < end;
        int s = ea ? g_col[i] : 0;
        float4 as = *(const float4*)(attS + s * 4);
        float e0 = as.x + ad.x; e0 = e0 > 0.f ? e0 : 0.2f * e0; e0 = __expf(e0);
        float e1 = as.y + ad.y; e1 = e1 > 0.f ? e1 : 0.2f * e1; e1 = __expf(e1);
        float e2 = as.z + ad.z; e2 = e2 > 0.f ? e2 : 0.2f * e2; e2 = __expf(e2);
        float e3 = as.w + ad.w; e3 = e3 > 0.f ? e3 : 0.2f * e3; e3 = __expf(e3);
        if (ea) { den0 += e0; den1 += e1; den2 += e2; den3 += e3; }
        sm_s[w][lane] = s;
        *(float4*)&sm_e[w][lane][0] = make_float4(e0, e1, e2, e3);
        __syncwarp();

        int cnt = end - i0; if (cnt > 32) cnt = 32;
        if (act) {
            for (int j = 0; j < cnt; j++) {
                int ss = sm_s[w][j];                    // uniform (broadcast LDS)
                float aa = sm_e[w][j][h0];              // 4-way LDS, conflict-free
                uint4 hv = *(const uint4*)(hbase + (size_t)ss * HC);
                float2 f0 = __half22float2(*(const half2*)&hv.x);
                float2 f1 = __half22float2(*(const half2*)&hv.y);
                float2 f2 = __half22float2(*(const half2*)&hv.z);
                float2 f3 = __half22float2(*(const half2*)&hv.w);
                acc[0] += aa * f0.x; acc[1] += aa * f0.y;
                acc[2] += aa * f1.x; acc[3] += aa * f1.y;
                acc[4] += aa * f2.x; acc[5] += aa * f2.y;
                acc[6] += aa * f3.x; acc[7] += aa * f3.y;
            }
        }
        __syncwarp();
    }

#pragma unroll
    for (int o = 16; o; o >>= 1) {
        den0 += __shfl_xor_sync(0xffffffffu, den0, o);
        den1 += __shfl_xor_sync(0xffffffffu, den1, o);
        den2 += __shfl_xor_sync(0xffffffffu, den2, o);
        den3 += __shfl_xor_sync(0xffffffffu, den3, o);
    }

    if (act) {
        float dd = h0 == 0 ? den0 : (h0 == 1 ? den1 : (h0 == 2 ? den2 : den3));
        float r = 1.f / dd;
        float4 b0 = *(const float4*)(bias + j0);
        float4 b1 = *(const float4*)(bias + j0 + 4);
        float o0[4], o1[4];
        o0[0] = acc[0] * r + b0.x; o0[1] = acc[1] * r + b0.y;
        o0[2] = acc[2] * r + b0.z; o0[3] = acc[3] * r + b0.w;
        o1[0] = acc[4] * r + b1.x; o1[1] = acc[5] * r + b1.y;
        o1[2] = acc[6] * r + b1.z; o1[3] = acc[7] * r + b1.w;
        if (do_relu) {
#pragma unroll
            for (int q = 0; q < 4; q++) {
                o0[q] = fmaxf(o0[q], 0.f);
                o1[q] = fmaxf(o1[q], 0.f);
            }
        }
        if (use_ext) {
            *(float4*)(out_ext + (size_t)d * HC + j0)     = make_float4(o0[0], o0[1], o0[2], o0[3]);
            *(float4*)(out_ext + (size_t)d * HC + j0 + 4) = make_float4(o1[0], o1[1], o1[2], o1[3]);
        } else {
            uint4 pk;
            pk.x = pack_h2(o0[0], o0[1]); pk.y = pack_h2(o0[2], o0[3]);
            pk.z = pack_h2(o1[0], o1[1]); pk.w = pack_h2(o1[2], o1[3]);
            *(uint4*)(g_out1h + (size_t)d * HC + j0) = pk;
        }
    }
}

// ---------------- launch ----------------
extern "C" void kernel_launch(void* const* d_in, const int* in_sizes, int n_in,
                              void* d_out, int out_size) {
    const float* x   = (const float*)d_in[0];
    const void*  ei  = d_in[1];
    const float* W1  = (const float*)d_in[2];
    const float* as1 = (const float*)d_in[3];
    const float* ad1 = (const float*)d_in[4];
    const float* b1  = (const float*)d_in[5];
    const float* W2  = (const float*)d_in[6];
    const float* as2 = (const float*)d_in[7];
    const float* ad2 = (const float*)d_in[8];
    const float* b2  = (const float*)d_in[9];

    int E = in_sizes[1] / 2;
    int HC1 = in_sizes[5];          // 256
    int HC2 = in_sizes[9];          // 160
    int F = in_sizes[2] / HC1;      // 128
    int N = in_sizes[0] / F;        // 50000
    int C1 = HC1 / 4;               // 64
    int C2 = HC2 / 4;               // 40
    int nW1 = in_sizes[2];
    int nW2 = in_sizes[6];

    // launches 0,1: column stats
    int nb = 200;
    int rowsPer = ceil_div(N, nb);
    colstats1<<<nb, FIN>>>(x, N, rowsPer);
    colstats2<<<1, FIN>>>(N, nb);

    // launch 2: standardize->fp16 + weight cvt + att zero
    {
        int work = N * (FIN / 8) + 4 * MAXN + nW1 + nW2;
        fin16_kernel<<<ceil_div(work, 256), 256>>>(x, W1, W2, N, nW1, nW2);
    }

    // launch 3: GEMM layer 1 (kept at index 3 for ncu capture)
    {
        dim3 grid(ceil_div(N, 128), ceil_div(HC1, 64));
        gemm_f16_kernel<128, 256, 64, 0><<<grid, 256>>>(as1, ad1, N);
    }

    // edge-dtype detect + counts init, then CSR build
    prep_kernel<<<ceil_div(N, 256) + 1, 256>>>((const unsigned int*)ei, E, N);
    csr_count<<<ceil_div(E, 256), 256>>>(ei, E);
    csr_scan<<<1, 1024>>>(N);
    csr_scatter<<<ceil_div(E + N, 256), 256>>>(ei, E, N);

    // ---- layer 1 aggregation ----
    agg_kernel<<<ceil_div(N, 8), 256>>>(b1, nullptr, 0, N, HC1, C1, 1, 0);

    // ---- layer 2 ----
    {
        dim3 grid(ceil_div(N, 128), ceil_div(HC2, 64));
        gemm_f16_kernel<256, 160, 40, 1><<<grid, 256>>>(as2, ad2, N);
    }
    agg_kernel<<<ceil_div(N, 8), 256>>>(b2, (float*)d_out, 1, N, HC2, C2, 0, 1);
}

// round 13
// speedup vs baseline: 2.4736x; 1.1414x over previous
#include <cuda_runtime.h>
#include <cuda_fp16.h>
#include <math.h>

// ---------------- problem capacity constants ----------------
#define MAXN 50000
#define MAXE 800000
#define MAXEL (MAXE + MAXN)   // edges + self loops
#define FIN 128
#define HC1MAX 256

#define PITCH_A 40   // halves; 80B rows, 16B-aligned, LDSM conflict-free
#define PITCH_B 72   // halves; 144B rows, 16B-aligned, LDSM conflict-free
#define ABYTES (128 * PITCH_A * 2)
#define BBYTES (32 * PITCH_B * 2)

// ---------------- device scratch (no allocations allowed) ----------------
__device__ __half g_xh[(MAXN + 128) * FIN];      // standardized x, fp16 (+pad rows)
__device__ __half g_h16[MAXN * HC1MAX];          // GEMM output (fp16), per layer
__device__ __half g_out1h[(MAXN + 128) * HC1MAX];// layer1 output (post relu), fp16 (+pad)
__device__ float  g_att[4 * MAXN * 4];           // [S1, D1, S2, D2] segments
__device__ __half g_w1h[HC1MAX * HC1MAX];        // W1 fp16
__device__ __half g_w2h[HC1MAX * HC1MAX];        // W2 fp16
__device__ int    g_counts[MAXN];
__device__ int    g_off[MAXN + 1];
__device__ int    g_cursor[MAXN];
__device__ int    g_col[MAXEL];
__device__ float  g_part[512 * 260];             // column-stat partials
__device__ float  g_mean[FIN];
__device__ float  g_istd[FIN];
__device__ int    g_is64;

static inline int ceil_div(int a, int b) { return (a + b - 1) / b; }

// ---------------- side stream + events (created once, before harness runs) --
struct SideCtx {
    cudaStream_t side;
    cudaEvent_t  e_fork, e_join;
    SideCtx() {
        cudaStreamCreateWithFlags(&side, cudaStreamNonBlocking);
        cudaEventCreateWithFlags(&e_fork, cudaEventDisableTiming);
        cudaEventCreateWithFlags(&e_join, cudaEventDisableTiming);
    }
};
static SideCtx g_sc;   // static-init: context + stream made at load time

__device__ __forceinline__ unsigned pack_h2(float lo, float hi) {
    __half2 h = __floats2half2_rn(lo, hi);
    return *(unsigned*)&h;
}

__device__ __forceinline__ void cp16(unsigned smem_addr, const void* gptr) {
    asm volatile("cp.async.ca.shared.global [%0], [%1], 16;"
                 :: "r"(smem_addr), "l"(gptr));
}

// ---------------- column stats (mean, std ddof=1) ----------------
__global__ void colstats1(const float* __restrict__ x, int N, int rowsPer) {
    int f = threadIdx.x;           // FIN threads
    int b = blockIdx.x;
    int r0 = b * rowsPer;
    int r1 = r0 + rowsPer; if (r1 > N) r1 = N;
    float s = 0.f, s2 = 0.f;
    for (int r = r0; r < r1; r++) {
        float v = x[(size_t)r * FIN + f];
        s += v; s2 += v * v;
    }
    g_part[b * 2 * FIN + f] = s;
    g_part[b * 2 * FIN + FIN + f] = s2;
}

__global__ void colstats2(int N, int nb) {
    int f = threadIdx.x;
    double s = 0.0, s2 = 0.0;
    for (int b = 0; b < nb; b++) {
        s  += (double)g_part[b * 2 * FIN + f];
        s2 += (double)g_part[b * 2 * FIN + FIN + f];
    }
    double mean = s / (double)N;
    double var = (s2 - s * s / (double)N) / (double)(N - 1);
    g_mean[f] = (float)mean;
    g_istd[f] = (float)(1.0 / sqrt(var));
}

// ---------------- fin16: standardize x -> fp16, weight cvt, att zero --------
__global__ void fin16_kernel(const float* __restrict__ x,
                             const float* __restrict__ W1,
                             const float* __restrict__ W2,
                             int N, int nW1, int nW2) {
    int idx = blockIdx.x * blockDim.x + threadIdx.x;
    int nStd = N * (FIN / 8);
    if (idx < nStd) {
        int f8 = (idx & (FIN / 8 - 1)) * 8;
        const float4* xp = (const float4*)x + (size_t)idx * 2;
        float4 v0 = xp[0], v1 = xp[1];
        float4 mn0 = *(const float4*)(g_mean + f8);
        float4 is0 = *(const float4*)(g_istd + f8);
        float4 mn1 = *(const float4*)(g_mean + f8 + 4);
        float4 is1 = *(const float4*)(g_istd + f8 + 4);
        uint4 o;
        o.x = pack_h2((v0.x - mn0.x) * is0.x, (v0.y - mn0.y) * is0.y);
        o.y = pack_h2((v0.z - mn0.z) * is0.z, (v0.w - mn0.w) * is0.w);
        o.z = pack_h2((v1.x - mn1.x) * is1.x, (v1.y - mn1.y) * is1.y);
        o.w = pack_h2((v1.z - mn1.z) * is1.z, (v1.w - mn1.w) * is1.w);
        *((uint4*)g_xh + idx) = o;
        return;
    }
    idx -= nStd;
    if (idx < 4 * MAXN) {                                 // zero att accumulators
        ((float4*)g_att)[idx] = make_float4(0.f, 0.f, 0.f, 0.f);
        return;
    }
    idx -= 4 * MAXN;
    if (idx < nW1) { g_w1h[idx] = __float2half_rn(W1[idx]); return; }
    idx -= nW1;
    if (idx < nW2) { g_w2h[idx] = __float2half_rn(W2[idx]); return; }
}

// ---------------- prep: edge-dtype detect + counts init ----------------
__global__ void prep_kernel(const unsigned int* p, int E, int N) {
    int b = blockIdx.x;
    if (b == gridDim.x - 1) {
        __shared__ unsigned int acc;
        if (threadIdx.x == 0) acc = 0u;
        __syncthreads();
        int n = E < 1024 ? E : 1024;
        unsigned int v = 0;
        for (int i = threadIdx.x; i < n; i += blockDim.x) v |= p[2 * i + 1];
        atomicOr(&acc, v);
        __syncthreads();
        if (threadIdx.x == 0) g_is64 = (acc == 0u) ? 1 : 0;
        return;
    }
    int i = b * blockDim.x + threadIdx.x;
    if (i < N) g_counts[i] = 1;   // self loop
}

__device__ __forceinline__ void get_edge(const void* ei, int E, int k, int& s, int& d) {
    if (g_is64) {
        const long long* p = (const long long*)ei;
        s = (int)p[k]; d = (int)p[E + k];
    } else {
        const int* p = (const int*)ei;
        s = p[k]; d = p[E + k];
    }
}

// ---------------- CSR build (by dst, self-loops included) ----------------
__global__ void csr_count(const void* ei, int E) {
    int k = blockIdx.x * blockDim.x + threadIdx.x;
    if (k >= E) return;
    int s, d; get_edge(ei, E, k, s, d);
    atomicAdd(&g_counts[d], 1);
}

__global__ void csr_scan(int N) {
    __shared__ int sm[1024];
    int t = threadIdx.x;
    int chunk = (N + 1023) / 1024;
    int start = t * chunk;
    int end = start + chunk; if (end > N) end = N;
    int sum = 0;
    for (int i = start; i < end; i++) sum += g_counts[i];
    sm[t] = sum;
    __syncthreads();
    for (int o = 1; o < 1024; o <<= 1) {
        int v = (t >= o) ? sm[t - o] : 0;
        __syncthreads();
        sm[t] += v;
        __syncthreads();
    }
    int run = sm[t] - sum;   // exclusive
    for (int i = start; i < end; i++) {
        g_off[i] = run;
        g_cursor[i] = run;
        run += g_counts[i];
    }
    if (t == 1023) g_off[N] = sm[1023];
}

__global__ void csr_scatter(const void* ei, int E, int N) {
    int k = blockIdx.x * blockDim.x + threadIdx.x;
    if (k >= E + N) return;
    int s, d;
    if (k < E) get_edge(ei, E, k, s, d);
    else { s = k - E; d = s; }
    int pos = atomicAdd(&g_cursor[d], 1);
    g_col[pos] = s;
}

// ---------------- fp16 tensor-core GEMM (cp.async 2-stage + ldmatrix) --------
__device__ __forceinline__ void mma_f16(float* c, const unsigned* a, const unsigned* b) {
    asm volatile(
        "mma.sync.aligned.m16n8k16.row.col.f32.f16.f16.f32 "
        "{%0,%1,%2,%3}, {%4,%5,%6,%7}, {%8,%9}, {%0,%1,%2,%3};\n"
        : "+f"(c[0]), "+f"(c[1]), "+f"(c[2]), "+f"(c[3])
        : "r"(a[0]), "r"(a[1]), "r"(a[2]), "r"(a[3]), "r"(b[0]), "r"(b[1]));
}

template <int K, int M, int C, int ASEL>
__global__ __launch_bounds__(256, 4)
void gemm_f16_kernel(const float* __restrict__ att_s,
                     const float* __restrict__ att_d, int N) {
    __shared__ __half As[2][128 * PITCH_A];
    __shared__ __half Bs[2][32 * PITCH_B];

    const int t = threadIdx.x;
    const int lane = t & 31;
    const int warp = t >> 5;
    const int groupID = lane >> 2;
    const int tig = lane & 3;
    const int warp_m = warp >> 1;   // 0..3
    const int warp_n = warp & 1;    // 0..1

    const int row0 = blockIdx.x * 128;
    const int col0 = blockIdx.y * 64;

    const int aRow = t >> 1;          // 0..127
    const int aC0  = (t & 1) * 16;    // 0 or 16 (halves)
    const int bRow = t >> 3;          // 0..31
    const int bC0  = (t & 7) * 8;     // 0..56 (halves)

    const int gRowA = row0 + aRow;    // may exceed N; g_xh/g_out1h padded
    const int gColB = col0 + bC0;
    const bool bOK = gColB < M;

    const __half* __restrict__ Ag = ASEL ? g_out1h : g_xh;
    const __half* __restrict__ Wp = ASEL ? g_w2h : g_w1h;

    float acc[2][4][4];
#pragma unroll
    for (int i = 0; i < 2; i++)
#pragma unroll
        for (int j = 0; j < 4; j++)
#pragma unroll
            for (int c = 0; c < 4; c++) acc[i][j][c] = 0.f;

    constexpr int T = K >> 5;

    const unsigned sA = (unsigned)__cvta_generic_to_shared(&As[0][0]);
    const unsigned sB = (unsigned)__cvta_generic_to_shared(&Bs[0][0]);
    const unsigned aDst = sA + (unsigned)((aRow * PITCH_A + aC0) * 2);
    const unsigned bDst = sB + (unsigned)((bRow * PITCH_B + bC0) * 2);

    auto stage = [&](int kb, int buf) {
        const __half* ap = Ag + (size_t)gRowA * K + kb + aC0;
        cp16(aDst + buf * ABYTES, ap);
        cp16(aDst + buf * ABYTES + 16, ap + 8);
        if (bOK) {
            const __half* bp = Wp + (size_t)(kb + bRow) * M + gColB;
            cp16(bDst + buf * BBYTES, bp);
        }
    };

    stage(0, 0);
    asm volatile("cp.async.commit_group;");

    const int mbase = warp_m * 32;
    const int nbase = warp_n * 32;

    for (int tt = 0; tt < T; tt++) {
        const int cur = tt & 1;
        if (tt + 1 < T) {
            stage((tt + 1) * 32, cur ^ 1);
            asm volatile("cp.async.commit_group;");
            asm volatile("cp.async.wait_group 1;");
        } else {
            asm volatile("cp.async.wait_group 0;");
        }
        __syncthreads();

        const unsigned aB = sA + (unsigned)(cur * ABYTES);
        const unsigned bB = sB + (unsigned)(cur * BBYTES);
#pragma unroll
        for (int k16 = 0; k16 < 32; k16 += 16) {
            unsigned a[2][4], b[2][4];
#pragma unroll
            for (int im = 0; im < 2; im++) {
                unsigned addr = aB + (unsigned)(((mbase + im * 16 + (lane & 15)) * PITCH_A
                                                + k16 + (lane >> 4) * 8) * 2);
                asm volatile("ldmatrix.sync.aligned.m8n8.x4.shared.b16 {%0,%1,%2,%3}, [%4];"
                             : "=r"(a[im][0]), "=r"(a[im][1]), "=r"(a[im][2]), "=r"(a[im][3])
                             : "r"(addr));
            }
#pragma unroll
            for (int jp = 0; jp < 2; jp++) {
                unsigned addr = bB + (unsigned)(((k16 + ((lane >> 3) & 1) * 8 + (lane & 7)) * PITCH_B
                                                + nbase + jp * 16 + (lane >> 4) * 8) * 2);
                asm volatile("ldmatrix.sync.aligned.m8n8.x4.trans.shared.b16 {%0,%1,%2,%3}, [%4];"
                             : "=r"(b[jp][0]), "=r"(b[jp][1]), "=r"(b[jp][2]), "=r"(b[jp][3])
                             : "r"(addr));
            }
#pragma unroll
            for (int im = 0; im < 2; im++)
#pragma unroll
                for (int in_ = 0; in_ < 4; in_++)
                    mma_f16(acc[im][in_], a[im], &b[in_ >> 1][(in_ & 1) * 2]);
        }
        __syncthreads();
    }

    // ---- epilogue: fp16 h store ----
#pragma unroll
    for (int im = 0; im < 2; im++) {
        int r_ = row0 + warp_m * 32 + im * 16 + groupID;
#pragma unroll
        for (int in_ = 0; in_ < 4; in_++) {
            int c_ = col0 + warp_n * 32 + in_ * 8 + tig * 2;
            if (c_ < M) {
                if (r_ < N)
                    *(half2*)(g_h16 + (size_t)r_ * M + c_) =
                        __floats2half2_rn(acc[im][in_][0], acc[im][in_][1]);
                if (r_ + 8 < N)
                    *(half2*)(g_h16 + (size_t)(r_ + 8) * M + c_) =
                        __floats2half2_rn(acc[im][in_][2], acc[im][in_][3]);
            }
        }
    }

    // ---- epilogue: fused attention projections ----
    float* __restrict__ attS = g_att + (2 * ASEL) * (MAXN * 4);
    float* __restrict__ attD = g_att + (2 * ASEL + 1) * (MAXN * 4);
    const int w0 = col0 + warp_n * 32;
    if (w0 < M) {
        const int hlo = w0 / C;
        const int whi = (w0 + 31 < M - 1) ? (w0 + 31) : (M - 1);
        const int hhi = whi / C;            // warp-uniform; at most hlo+1

#pragma unroll
        for (int im = 0; im < 2; im++) {
#pragma unroll
            for (int hf = 0; hf < 2; hf++) {
                int r_ = row0 + warp_m * 32 + im * 16 + groupID + hf * 8;
                float ps0 = 0.f, ps1 = 0.f, pd0 = 0.f, pd1 = 0.f;
#pragma unroll
                for (int in_ = 0; in_ < 4; in_++) {
                    int c = w0 + in_ * 8 + tig * 2;
                    if (c < M) {
                        float a0 = acc[im][in_][hf * 2 + 0];
                        float a1 = acc[im][in_][hf * 2 + 1];
                        float sv = a0 * att_s[c] + a1 * att_s[c + 1];
                        float dv = a0 * att_d[c] + a1 * att_d[c + 1];
                        if (c / C != hlo) { ps1 += sv; pd1 += dv; }
                        else              { ps0 += sv; pd0 += dv; }
                    }
                }
                ps0 += __shfl_xor_sync(0xffffffffu, ps0, 1);
                ps0 += __shfl_xor_sync(0xffffffffu, ps0, 2);
                pd0 += __shfl_xor_sync(0xffffffffu, pd0, 1);
                pd0 += __shfl_xor_sync(0xffffffffu, pd0, 2);
                if (tig == 0 && r_ < N) {
                    atomicAdd(&attS[r_ * 4 + hlo], ps0);
                    atomicAdd(&attD[r_ * 4 + hlo], pd0);
                }
                if (hhi > hlo) {
                    ps1 += __shfl_xor_sync(0xffffffffu, ps1, 1);
                    ps1 += __shfl_xor_sync(0xffffffffu, ps1, 2);
                    pd1 += __shfl_xor_sync(0xffffffffu, pd1, 1);
                    pd1 += __shfl_xor_sync(0xffffffffu, pd1, 2);
                    if (tig == 0 && r_ < N) {
                        atomicAdd(&attS[r_ * 4 + hhi], ps1);
                        atomicAdd(&attD[r_ * 4 + hhi], pd1);
                    }
                }
            }
        }
    }
}

// ---------------- single-pass aggregation: warp per dst ----------------
// Chunked e-prep + gather with distance-2 row prefetch (MLP 3 per warp).
__global__ __launch_bounds__(256)
void agg_kernel(const float* __restrict__ bias, float* __restrict__ out_ext,
                int use_ext, int N, int HC, int C, int do_relu, int layer) {
    __shared__ float sm_e[8][32][4];
    __shared__ int   sm_s[8][32];
    const float* __restrict__ attS = g_att + (2 * layer) * (MAXN * 4);
    const float* __restrict__ attD = g_att + (2 * layer + 1) * (MAXN * 4);
    int w = threadIdx.x >> 5;
    int warp = (blockIdx.x * blockDim.x + threadIdx.x) >> 5;
    int lane = threadIdx.x & 31;
    if (warp >= N) return;
    int d = warp;
    int beg = g_off[d], end = g_off[d + 1];
    float4 ad = *(const float4*)(attD + d * 4);

    int j0 = lane * 8;                 // 8 halves per lane
    bool act = j0 < HC;                // HC=256: all lanes; HC=160: lanes 0..19
    int h0 = act ? (j0 / C) : 0;       // head for this lane's block (8 | C)
    const __half* __restrict__ hbase = g_h16 + j0;

    float acc[8];
#pragma unroll
    for (int q = 0; q < 8; q++) acc[q] = 0.f;
    float den0 = 0.f, den1 = 0.f, den2 = 0.f, den3 = 0.f;

    for (int i0 = beg; i0 < end; i0 += 32) {
        int i = i0 + lane;
        bool ea = i < end;
        int s = ea ? g_col[i] : 0;
        float4 as = *(const float4*)(attS + s * 4);
        float e0 = as.x + ad.x; e0 = e0 > 0.f ? e0 : 0.2f * e0; e0 = __expf(e0);
        float e1 = as.y + ad.y; e1 = e1 > 0.f ? e1 : 0.2f * e1; e1 = __expf(e1);
        float e2 = as.z + ad.z; e2 = e2 > 0.f ? e2 : 0.2f * e2; e2 = __expf(e2);
        float e3 = as.w + ad.w; e3 = e3 > 0.f ? e3 : 0.2f * e3; e3 = __expf(e3);
        if (ea) { den0 += e0; den1 += e1; den2 += e2; den3 += e3; }
        sm_s[w][lane] = s;
        *(float4*)&sm_e[w][lane][0] = make_float4(e0, e1, e2, e3);
        __syncwarp();

        int cnt = end - i0; if (cnt > 32) cnt = 32;
        if (act) {
            // distance-2 software pipeline over the chunk (clamped prefetch idx)
            uint4 hv0 = *(const uint4*)(hbase + (size_t)sm_s[w][0] * HC);
            int i1 = cnt > 1 ? 1 : 0;
            uint4 hv1 = *(const uint4*)(hbase + (size_t)sm_s[w][i1] * HC);
            for (int j = 0; j < cnt; j++) {
                int jn = j + 2 < cnt ? j + 2 : cnt - 1;
                uint4 hv2 = *(const uint4*)(hbase + (size_t)sm_s[w][jn] * HC);
                float aa = sm_e[w][j][h0];              // 4-way LDS, conflict-free
                float2 f0 = __half22float2(*(const half2*)&hv0.x);
                float2 f1 = __half22float2(*(const half2*)&hv0.y);
                float2 f2 = __half22float2(*(const half2*)&hv0.z);
                float2 f3 = __half22float2(*(const half2*)&hv0.w);
                acc[0] += aa * f0.x; acc[1] += aa * f0.y;
                acc[2] += aa * f1.x; acc[3] += aa * f1.y;
                acc[4] += aa * f2.x; acc[5] += aa * f2.y;
                acc[6] += aa * f3.x; acc[7] += aa * f3.y;
                hv0 = hv1; hv1 = hv2;
            }
        }
        __syncwarp();
    }

#pragma unroll
    for (int o = 16; o; o >>= 1) {
        den0 += __shfl_xor_sync(0xffffffffu, den0, o);
        den1 += __shfl_xor_sync(0xffffffffu, den1, o);
        den2 += __shfl_xor_sync(0xffffffffu, den2, o);
        den3 += __shfl_xor_sync(0xffffffffu, den3, o);
    }

    if (act) {
        float dd = h0 == 0 ? den0 : (h0 == 1 ? den1 : (h0 == 2 ? den2 : den3));
        float r = 1.f / dd;
        float4 b0 = *(const float4*)(bias + j0);
        float4 b1 = *(const float4*)(bias + j0 + 4);
        float o0[4], o1[4];
        o0[0] = acc[0] * r + b0.x; o0[1] = acc[1] * r + b0.y;
        o0[2] = acc[2] * r + b0.z; o0[3] = acc[3] * r + b0.w;
        o1[0] = acc[4] * r + b1.x; o1[1] = acc[5] * r + b1.y;
        o1[2] = acc[6] * r + b1.z; o1[3] = acc[7] * r + b1.w;
        if (do_relu) {
#pragma unroll
            for (int q = 0; q < 4; q++) {
                o0[q] = fmaxf(o0[q], 0.f);
                o1[q] = fmaxf(o1[q], 0.f);
            }
        }
        if (use_ext) {
            *(float4*)(out_ext + (size_t)d * HC + j0)     = make_float4(o0[0], o0[1], o0[2], o0[3]);
            *(float4*)(out_ext + (size_t)d * HC + j0 + 4) = make_float4(o1[0], o1[1], o1[2], o1[3]);
        } else {
            uint4 pk;
            pk.x = pack_h2(o0[0], o0[1]); pk.y = pack_h2(o0[2], o0[3]);
            pk.z = pack_h2(o1[0], o1[1]); pk.w = pack_h2(o1[2], o1[3]);
            *(uint4*)(g_out1h + (size_t)d * HC + j0) = pk;
        }
    }
}

// ---------------- launch ----------------
extern "C" void kernel_launch(void* const* d_in, const int* in_sizes, int n_in,
                              void* d_out, int out_size) {
    const float* x   = (const float*)d_in[0];
    const void*  ei  = d_in[1];
    const float* W1  = (const float*)d_in[2];
    const float* as1 = (const float*)d_in[3];
    const float* ad1 = (const float*)d_in[4];
    const float* b1  = (const float*)d_in[5];
    const float* W2  = (const float*)d_in[6];
    const float* as2 = (const float*)d_in[7];
    const float* ad2 = (const float*)d_in[8];
    const float* b2  = (const float*)d_in[9];

    int E = in_sizes[1] / 2;
    int HC1 = in_sizes[5];          // 256
    int HC2 = in_sizes[9];          // 160
    int F = in_sizes[2] / HC1;      // 128
    int N = in_sizes[0] / F;        // 50000
    int C1 = HC1 / 4;               // 64
    int C2 = HC2 / 4;               // 40
    int nW1 = in_sizes[2];
    int nW2 = in_sizes[6];

    // fork point for the independent CSR chain
    cudaEventRecord(g_sc.e_fork, 0);

    // ---- main chain (legacy stream): stats -> fin16 -> gemm1 ----
    int nb = 400;
    int rowsPer = ceil_div(N, nb);
    colstats1<<<nb, FIN>>>(x, N, rowsPer);                          // launch 0
    colstats2<<<1, FIN>>>(N, nb);                                   // launch 1
    {
        int work = N * (FIN / 8) + 4 * MAXN + nW1 + nW2;
        fin16_kernel<<<ceil_div(work, 256), 256>>>(x, W1, W2, N, nW1, nW2); // 2
    }
    {
        dim3 grid(ceil_div(N, 128), ceil_div(HC1, 64));
        gemm_f16_kernel<128, 256, 64, 0><<<grid, 256>>>(as1, ad1, N);       // 3
    }

    // ---- side chain: edge detect + CSR build (independent of main chain) ----
    cudaStreamWaitEvent(g_sc.side, g_sc.e_fork, 0);
    prep_kernel<<<ceil_div(N, 256) + 1, 256, 0, g_sc.side>>>(
        (const unsigned int*)ei, E, N);
    csr_count<<<ceil_div(E, 256), 256, 0, g_sc.side>>>(ei, E);
    csr_scan<<<1, 1024, 0, g_sc.side>>>(N);
    csr_scatter<<<ceil_div(E + N, 256), 256, 0, g_sc.side>>>(ei, E, N);
    cudaEventRecord(g_sc.e_join, g_sc.side);

    // join: agg1 needs both gemm1 (legacy) and CSR (side)
    cudaStreamWaitEvent(0, g_sc.e_join, 0);

    // ---- layer 1 aggregation ----
    agg_kernel<<<ceil_div(N, 8), 256>>>(b1, nullptr, 0, N, HC1, C1, 1, 0);

    // ---- layer 2 ----
    {
        dim3 grid(ceil_div(N, 128), ceil_div(HC2, 64));
        gemm_f16_kernel<256, 160, 40, 1><<<grid, 256>>>(as2, ad2, N);
    }
    agg_kernel<<<ceil_div(N, 8), 256>>>(b2, (float*)d_out, 1, N, HC2, C2, 0, 1);
}

// round 14
// speedup vs baseline: 2.4831x; 1.0038x over previous
#include <cuda_runtime.h>
#include <cuda_fp16.h>
#include <math.h>

// ---------------- problem capacity constants ----------------
#define MAXN 50000
#define MAXE 800000
#define MAXEL (MAXE + MAXN)   // edges + self loops
#define FIN 128
#define HC1MAX 256

#define PITCH_A 40   // halves; 80B rows, 16B-aligned, LDSM conflict-free
#define PITCH_B 72   // halves; 144B rows, 16B-aligned, LDSM conflict-free
#define ABYTES (128 * PITCH_A * 2)
#define BBYTES (32 * PITCH_B * 2)
#define NSTAGE 3

// ---------------- device scratch (no allocations allowed) ----------------
__device__ __half g_xh[(MAXN + 128) * FIN];      // standardized x, fp16 (+pad rows)
__device__ __half g_h16[MAXN * HC1MAX];          // GEMM output (fp16), per layer
__device__ __half g_out1h[(MAXN + 128) * HC1MAX];// layer1 output (post relu), fp16 (+pad)
__device__ float  g_att[4 * MAXN * 4];           // [S1, D1, S2, D2] segments
__device__ __half g_w1h[HC1MAX * HC1MAX];        // W1 fp16
__device__ __half g_w2h[HC1MAX * HC1MAX];        // W2 fp16
__device__ int    g_counts[MAXN];
__device__ int    g_off[MAXN + 1];
__device__ int    g_cursor[MAXN];
__device__ int    g_col[MAXEL];
__device__ float  g_part[512 * 260];             // column-stat partials
__device__ float  g_mean[FIN];
__device__ float  g_istd[FIN];
__device__ int    g_is64;

static inline int ceil_div(int a, int b) { return (a + b - 1) / b; }

// ---------------- side stream + events (created once, before harness runs) --
struct SideCtx {
    cudaStream_t side;
    cudaEvent_t  e_fork, e_join;
    SideCtx() {
        cudaStreamCreateWithFlags(&side, cudaStreamNonBlocking);
        cudaEventCreateWithFlags(&e_fork, cudaEventDisableTiming);
        cudaEventCreateWithFlags(&e_join, cudaEventDisableTiming);
    }
};
static SideCtx g_sc;   // static-init: context + stream made at load time

__device__ __forceinline__ unsigned pack_h2(float lo, float hi) {
    __half2 h = __floats2half2_rn(lo, hi);
    return *(unsigned*)&h;
}

__device__ __forceinline__ void cp16(unsigned smem_addr, const void* gptr) {
    asm volatile("cp.async.ca.shared.global [%0], [%1], 16;"
                 :: "r"(smem_addr), "l"(gptr));
}

// ---------------- column stats (mean, std ddof=1) ----------------
__global__ void colstats1(const float* __restrict__ x, int N, int rowsPer) {
    int f = threadIdx.x;           // FIN threads
    int b = blockIdx.x;
    int r0 = b * rowsPer;
    int r1 = r0 + rowsPer; if (r1 > N) r1 = N;
    float s = 0.f, s2 = 0.f;
    for (int r = r0; r < r1; r++) {
        float v = x[(size_t)r * FIN + f];
        s += v; s2 += v * v;
    }
    g_part[b * 2 * FIN + f] = s;
    g_part[b * 2 * FIN + FIN + f] = s2;
}

// 512 threads: feature f = t&127, group g = t>>7 sums strided quarter of blocks
__global__ void colstats2(int N, int nb) {
    __shared__ double sm_s[4][FIN], sm_s2[4][FIN];
    int f = threadIdx.x & 127;
    int g = threadIdx.x >> 7;
    double s = 0.0, s2 = 0.0;
    for (int b = g; b < nb; b += 4) {
        s  += (double)g_part[b * 2 * FIN + f];
        s2 += (double)g_part[b * 2 * FIN + FIN + f];
    }
    sm_s[g][f] = s; sm_s2[g][f] = s2;
    __syncthreads();
    if (g == 0) {
        s  = sm_s[0][f]  + sm_s[1][f]  + sm_s[2][f]  + sm_s[3][f];
        s2 = sm_s2[0][f] + sm_s2[1][f] + sm_s2[2][f] + sm_s2[3][f];
        double mean = s / (double)N;
        double var = (s2 - s * s / (double)N) / (double)(N - 1);
        g_mean[f] = (float)mean;
        g_istd[f] = (float)(1.0 / sqrt(var));
    }
}

// ---------------- fin16: standardize x -> fp16, weight cvt, att zero --------
__global__ void fin16_kernel(const float* __restrict__ x,
                             const float* __restrict__ W1,
                             const float* __restrict__ W2,
                             int N, int nW1, int nW2) {
    int idx = blockIdx.x * blockDim.x + threadIdx.x;
    int nStd = N * (FIN / 8);
    if (idx < nStd) {
        int f8 = (idx & (FIN / 8 - 1)) * 8;
        const float4* xp = (const float4*)x + (size_t)idx * 2;
        float4 v0 = xp[0], v1 = xp[1];
        float4 mn0 = *(const float4*)(g_mean + f8);
        float4 is0 = *(const float4*)(g_istd + f8);
        float4 mn1 = *(const float4*)(g_mean + f8 + 4);
        float4 is1 = *(const float4*)(g_istd + f8 + 4);
        uint4 o;
        o.x = pack_h2((v0.x - mn0.x) * is0.x, (v0.y - mn0.y) * is0.y);
        o.y = pack_h2((v0.z - mn0.z) * is0.z, (v0.w - mn0.w) * is0.w);
        o.z = pack_h2((v1.x - mn1.x) * is1.x, (v1.y - mn1.y) * is1.y);
        o.w = pack_h2((v1.z - mn1.z) * is1.z, (v1.w - mn1.w) * is1.w);
        *((uint4*)g_xh + idx) = o;
        return;
    }
    idx -= nStd;
    if (idx < 4 * MAXN) {                                 // zero att accumulators
        ((float4*)g_att)[idx] = make_float4(0.f, 0.f, 0.f, 0.f);
        return;
    }
    idx -= 4 * MAXN;
    if (idx < nW1) { g_w1h[idx] = __float2half_rn(W1[idx]); return; }
    idx -= nW1;
    if (idx < nW2) { g_w2h[idx] = __float2half_rn(W2[idx]); return; }
}

// ---------------- prep: edge-dtype detect + counts init ----------------
__global__ void prep_kernel(const unsigned int* p, int E, int N) {
    int b = blockIdx.x;
    if (b == gridDim.x - 1) {
        __shared__ unsigned int acc;
        if (threadIdx.x == 0) acc = 0u;
        __syncthreads();
        int n = E < 1024 ? E : 1024;
        unsigned int v = 0;
        for (int i = threadIdx.x; i < n; i += blockDim.x) v |= p[2 * i + 1];
        atomicOr(&acc, v);
        __syncthreads();
        if (threadIdx.x == 0) g_is64 = (acc == 0u) ? 1 : 0;
        return;
    }
    int i = b * blockDim.x + threadIdx.x;
    if (i < N) g_counts[i] = 1;   // self loop
}

__device__ __forceinline__ void get_edge(const void* ei, int E, int k, int& s, int& d) {
    if (g_is64) {
        const long long* p = (const long long*)ei;
        s = (int)p[k]; d = (int)p[E + k];
    } else {
        const int* p = (const int*)ei;
        s = p[k]; d = p[E + k];
    }
}

// ---------------- CSR build (by dst, self-loops included) ----------------
__global__ void csr_count(const void* ei, int E) {
    int k = blockIdx.x * blockDim.x + threadIdx.x;
    if (k >= E) return;
    int s, d; get_edge(ei, E, k, s, d);
    atomicAdd(&g_counts[d], 1);
}

__global__ void csr_scan(int N) {
    __shared__ int sm[1024];
    int t = threadIdx.x;
    int chunk = (N + 1023) / 1024;
    int start = t * chunk;
    int end = start + chunk; if (end > N) end = N;
    int sum = 0;
    for (int i = start; i < end; i++) sum += g_counts[i];
    sm[t] = sum;
    __syncthreads();
    for (int o = 1; o < 1024; o <<= 1) {
        int v = (t >= o) ? sm[t - o] : 0;
        __syncthreads();
        sm[t] += v;
        __syncthreads();
    }
    int run = sm[t] - sum;   // exclusive
    for (int i = start; i < end; i++) {
        g_off[i] = run;
        g_cursor[i] = run;
        run += g_counts[i];
    }
    if (t == 1023) g_off[N] = sm[1023];
}

__global__ void csr_scatter(const void* ei, int E, int N) {
    int k = blockIdx.x * blockDim.x + threadIdx.x;
    if (k >= E + N) return;
    int s, d;
    if (k < E) get_edge(ei, E, k, s, d);
    else { s = k - E; d = s; }
    int pos = atomicAdd(&g_cursor[d], 1);
    g_col[pos] = s;
}

// ---------------- fp16 tensor-core GEMM (cp.async 3-stage ring + ldmatrix) ---
__device__ __forceinline__ void mma_f16(float* c, const unsigned* a, const unsigned* b) {
    asm volatile(
        "mma.sync.aligned.m16n8k16.row.col.f32.f16.f16.f32 "
        "{%0,%1,%2,%3}, {%4,%5,%6,%7}, {%8,%9}, {%0,%1,%2,%3};\n"
        : "+f"(c[0]), "+f"(c[1]), "+f"(c[2]), "+f"(c[3])
        : "r"(a[0]), "r"(a[1]), "r"(a[2]), "r"(a[3]), "r"(b[0]), "r"(b[1]));
}

template <int K, int M, int C, int ASEL>
__global__ __launch_bounds__(256, 4)
void gemm_f16_kernel(const float* __restrict__ att_s,
                     const float* __restrict__ att_d, int N) {
    __shared__ __half As[NSTAGE][128 * PITCH_A];
    __shared__ __half Bs[NSTAGE][32 * PITCH_B];

    const int t = threadIdx.x;
    const int lane = t & 31;
    const int warp = t >> 5;
    const int groupID = lane >> 2;
    const int tig = lane & 3;
    const int warp_m = warp >> 1;   // 0..3
    const int warp_n = warp & 1;    // 0..1

    const int row0 = blockIdx.x * 128;
    const int col0 = blockIdx.y * 64;

    const int aRow = t >> 1;          // 0..127
    const int aC0  = (t & 1) * 16;    // 0 or 16 (halves)
    const int bRow = t >> 3;          // 0..31
    const int bC0  = (t & 7) * 8;     // 0..56 (halves)

    const int gRowA = row0 + aRow;    // may exceed N; g_xh/g_out1h padded
    const int gColB = col0 + bC0;
    const bool bOK = gColB < M;

    const __half* __restrict__ Ag = ASEL ? g_out1h : g_xh;
    const __half* __restrict__ Wp = ASEL ? g_w2h : g_w1h;

    float acc[2][4][4];
#pragma unroll
    for (int i = 0; i < 2; i++)
#pragma unroll
        for (int j = 0; j < 4; j++)
#pragma unroll
            for (int c = 0; c < 4; c++) acc[i][j][c] = 0.f;

    constexpr int T = K >> 5;

    const unsigned sA = (unsigned)__cvta_generic_to_shared(&As[0][0]);
    const unsigned sB = (unsigned)__cvta_generic_to_shared(&Bs[0][0]);
    const unsigned aDst = sA + (unsigned)((aRow * PITCH_A + aC0) * 2);
    const unsigned bDst = sB + (unsigned)((bRow * PITCH_B + bC0) * 2);

    auto stage = [&](int kb, int buf) {
        const __half* ap = Ag + (size_t)gRowA * K + kb + aC0;
        cp16(aDst + buf * ABYTES, ap);
        cp16(aDst + buf * ABYTES + 16, ap + 8);
        if (bOK) {
            const __half* bp = Wp + (size_t)(kb + bRow) * M + gColB;
            cp16(bDst + buf * BBYTES, bp);
        }
    };

    // ---- prologue: fill the ring ----
#pragma unroll
    for (int s = 0; s < NSTAGE; s++) {
        if (s < T) stage(s * 32, s);
        asm volatile("cp.async.commit_group;");
    }

    const int mbase = warp_m * 32;
    const int nbase = warp_n * 32;

#pragma unroll
    for (int tt = 0; tt < T; tt++) {
        const int cur = tt % NSTAGE;
        asm volatile("cp.async.wait_group %0;" :: "n"(NSTAGE - 1));
        __syncthreads();

        const unsigned aB = sA + (unsigned)(cur * ABYTES);
        const unsigned bB = sB + (unsigned)(cur * BBYTES);
#pragma unroll
        for (int k16 = 0; k16 < 32; k16 += 16) {
            unsigned a[2][4], b[2][4];
#pragma unroll
            for (int im = 0; im < 2; im++) {
                unsigned addr = aB + (unsigned)(((mbase + im * 16 + (lane & 15)) * PITCH_A
                                                + k16 + (lane >> 4) * 8) * 2);
                asm volatile("ldmatrix.sync.aligned.m8n8.x4.shared.b16 {%0,%1,%2,%3}, [%4];"
                             : "=r"(a[im][0]), "=r"(a[im][1]), "=r"(a[im][2]), "=r"(a[im][3])
                             : "r"(addr));
            }
#pragma unroll
            for (int jp = 0; jp < 2; jp++) {
                unsigned addr = bB + (unsigned)(((k16 + ((lane >> 3) & 1) * 8 + (lane & 7)) * PITCH_B
                                                + nbase + jp * 16 + (lane >> 4) * 8) * 2);
                asm volatile("ldmatrix.sync.aligned.m8n8.x4.trans.shared.b16 {%0,%1,%2,%3}, [%4];"
                             : "=r"(b[jp][0]), "=r"(b[jp][1]), "=r"(b[jp][2]), "=r"(b[jp][3])
                             : "r"(addr));
            }
#pragma unroll
            for (int im = 0; im < 2; im++)
#pragma unroll
                for (int in_ = 0; in_ < 4; in_++)
                    mma_f16(acc[im][in_], a[im], &b[in_ >> 1][(in_ & 1) * 2]);
        }
        __syncthreads();
        if (tt + NSTAGE < T) stage((tt + NSTAGE) * 32, cur);
        asm volatile("cp.async.commit_group;");   // possibly empty group
    }

    // ---- epilogue: fp16 h store ----
#pragma unroll
    for (int im = 0; im < 2; im++) {
        int r_ = row0 + warp_m * 32 + im * 16 + groupID;
#pragma unroll
        for (int in_ = 0; in_ < 4; in_++) {
            int c_ = col0 + warp_n * 32 + in_ * 8 + tig * 2;
            if (c_ < M) {
                if (r_ < N)
                    *(half2*)(g_h16 + (size_t)r_ * M + c_) =
                        __floats2half2_rn(acc[im][in_][0], acc[im][in_][1]);
                if (r_ + 8 < N)
                    *(half2*)(g_h16 + (size_t)(r_ + 8) * M + c_) =
                        __floats2half2_rn(acc[im][in_][2], acc[im][in_][3]);
            }
        }
    }

    // ---- epilogue: fused attention projections ----
    float* __restrict__ attS = g_att + (2 * ASEL) * (MAXN * 4);
    float* __restrict__ attD = g_att + (2 * ASEL + 1) * (MAXN * 4);
    const int w0 = col0 + warp_n * 32;
    if (w0 < M) {
        const int hlo = w0 / C;
        const int whi = (w0 + 31 < M - 1) ? (w0 + 31) : (M - 1);
        const int hhi = whi / C;            // warp-uniform; at most hlo+1

#pragma unroll
        for (int im = 0; im < 2; im++) {
#pragma unroll
            for (int hf = 0; hf < 2; hf++) {
                int r_ = row0 + warp_m * 32 + im * 16 + groupID + hf * 8;
                float ps0 = 0.f, ps1 = 0.f, pd0 = 0.f, pd1 = 0.f;
#pragma unroll
                for (int in_ = 0; in_ < 4; in_++) {
                    int c = w0 + in_ * 8 + tig * 2;
                    if (c < M) {
                        float a0 = acc[im][in_][hf * 2 + 0];
                        float a1 = acc[im][in_][hf * 2 + 1];
                        float sv = a0 * att_s[c] + a1 * att_s[c + 1];
                        float dv = a0 * att_d[c] + a1 * att_d[c + 1];
                        if (c / C != hlo) { ps1 += sv; pd1 += dv; }
                        else              { ps0 += sv; pd0 += dv; }
                    }
                }
                ps0 += __shfl_xor_sync(0xffffffffu, ps0, 1);
                ps0 += __shfl_xor_sync(0xffffffffu, ps0, 2);
                pd0 += __shfl_xor_sync(0xffffffffu, pd0, 1);
                pd0 += __shfl_xor_sync(0xffffffffu, pd0, 2);
                if (tig == 0 && r_ < N) {
                    atomicAdd(&attS[r_ * 4 + hlo], ps0);
                    atomicAdd(&attD[r_ * 4 + hlo], pd0);
                }
                if (hhi > hlo) {
                    ps1 += __shfl_xor_sync(0xffffffffu, ps1, 1);
                    ps1 += __shfl_xor_sync(0xffffffffu, ps1, 2);
                    pd1 += __shfl_xor_sync(0xffffffffu, pd1, 1);
                    pd1 += __shfl_xor_sync(0xffffffffu, pd1, 2);
                    if (tig == 0 && r_ < N) {
                        atomicAdd(&attS[r_ * 4 + hhi], ps1);
                        atomicAdd(&attD[r_ * 4 + hhi], pd1);
                    }
                }
            }
        }
    }
}

// ---------------- single-pass aggregation: warp per dst ----------------
// Chunked e-prep + gather with distance-2 row prefetch (MLP 3 per warp).
__global__ __launch_bounds__(256)
void agg_kernel(const float* __restrict__ bias, float* __restrict__ out_ext,
                int use_ext, int N, int HC, int C, int do_relu, int layer) {
    __shared__ float sm_e[8][32][4];
    __shared__ int   sm_s[8][32];
    const float* __restrict__ attS = g_att + (2 * layer) * (MAXN * 4);
    const float* __restrict__ attD = g_att + (2 * layer + 1) * (MAXN * 4);
    int w = threadIdx.x >> 5;
    int warp = (blockIdx.x * blockDim.x + threadIdx.x) >> 5;
    int lane = threadIdx.x & 31;
    if (warp >= N) return;
    int d = warp;
    int beg = g_off[d], end = g_off[d + 1];
    float4 ad = *(const float4*)(attD + d * 4);

    int j0 = lane * 8;                 // 8 halves per lane
    bool act = j0 < HC;                // HC=256: all lanes; HC=160: lanes 0..19
    int h0 = act ? (j0 / C) : 0;       // head for this lane's block (8 | C)
    const __half* __restrict__ hbase = g_h16 + j0;

    float acc[8];
#pragma unroll
    for (int q = 0; q < 8; q++) acc[q] = 0.f;
    float den0 = 0.f, den1 = 0.f, den2 = 0.f, den3 = 0.f;

    for (int i0 = beg; i0 < end; i0 += 32) {
        int i = i0 + lane;
        bool ea = i < end;
        int s = ea ? g_col[i] : 0;
        float4 as = *(const float4*)(attS + s * 4);
        float e0 = as.x + ad.x; e0 = e0 > 0.f ? e0 : 0.2f * e0; e0 = __expf(e0);
        float e1 = as.y + ad.y; e1 = e1 > 0.f ? e1 : 0.2f * e1; e1 = __expf(e1);
        float e2 = as.z + ad.z; e2 = e2 > 0.f ? e2 : 0.2f * e2; e2 = __expf(e2);
        float e3 = as.w + ad.w; e3 = e3 > 0.f ? e3 : 0.2f * e3; e3 = __expf(e3);
        if (ea) { den0 += e0; den1 += e1; den2 += e2; den3 += e3; }
        sm_s[w][lane] = s;
        *(float4*)&sm_e[w][lane][0] = make_float4(e0, e1, e2, e3);
        __syncwarp();

        int cnt = end - i0; if (cnt > 32) cnt = 32;
        if (act) {
            // distance-2 software pipeline over the chunk (clamped prefetch idx)
            uint4 hv0 = *(const uint4*)(hbase + (size_t)sm_s[w][0] * HC);
            int i1 = cnt > 1 ? 1 : 0;
            uint4 hv1 = *(const uint4*)(hbase + (size_t)sm_s[w][i1] * HC);
            for (int j = 0; j < cnt; j++) {
                int jn = j + 2 < cnt ? j + 2 : cnt - 1;
                uint4 hv2 = *(const uint4*)(hbase + (size_t)sm_s[w][jn] * HC);
                float aa = sm_e[w][j][h0];              // 4-way LDS, conflict-free
                float2 f0 = __half22float2(*(const half2*)&hv0.x);
                float2 f1 = __half22float2(*(const half2*)&hv0.y);
                float2 f2 = __half22float2(*(const half2*)&hv0.z);
                float2 f3 = __half22float2(*(const half2*)&hv0.w);
                acc[0] += aa * f0.x; acc[1] += aa * f0.y;
                acc[2] += aa * f1.x; acc[3] += aa * f1.y;
                acc[4] += aa * f2.x; acc[5] += aa * f2.y;
                acc[6] += aa * f3.x; acc[7] += aa * f3.y;
                hv0 = hv1; hv1 = hv2;
            }
        }
        __syncwarp();
    }

#pragma unroll
    for (int o = 16; o; o >>= 1) {
        den0 += __shfl_xor_sync(0xffffffffu, den0, o);
        den1 += __shfl_xor_sync(0xffffffffu, den1, o);
        den2 += __shfl_xor_sync(0xffffffffu, den2, o);
        den3 += __shfl_xor_sync(0xffffffffu, den3, o);
    }

    if (act) {
        float dd = h0 == 0 ? den0 : (h0 == 1 ? den1 : (h0 == 2 ? den2 : den3));
        float r = 1.f / dd;
        float4 b0 = *(const float4*)(bias + j0);
        float4 b1 = *(const float4*)(bias + j0 + 4);
        float o0[4], o1[4];
        o0[0] = acc[0] * r + b0.x; o0[1] = acc[1] * r + b0.y;
        o0[2] = acc[2] * r + b0.z; o0[3] = acc[3] * r + b0.w;
        o1[0] = acc[4] * r + b1.x; o1[1] = acc[5] * r + b1.y;
        o1[2] = acc[6] * r + b1.z; o1[3] = acc[7] * r + b1.w;
        if (do_relu) {
#pragma unroll
            for (int q = 0; q < 4; q++) {
                o0[q] = fmaxf(o0[q], 0.f);
                o1[q] = fmaxf(o1[q], 0.f);
            }
        }
        if (use_ext) {
            *(float4*)(out_ext + (size_t)d * HC + j0)     = make_float4(o0[0], o0[1], o0[2], o0[3]);
            *(float4*)(out_ext + (size_t)d * HC + j0 + 4) = make_float4(o1[0], o1[1], o1[2], o1[3]);
        } else {
            uint4 pk;
            pk.x = pack_h2(o0[0], o0[1]); pk.y = pack_h2(o0[2], o0[3]);
            pk.z = pack_h2(o1[0], o1[1]); pk.w = pack_h2(o1[2], o1[3]);
            *(uint4*)(g_out1h + (size_t)d * HC + j0) = pk;
        }
    }
}

// ---------------- launch ----------------
extern "C" void kernel_launch(void* const* d_in, const int* in_sizes, int n_in,
                              void* d_out, int out_size) {
    const float* x   = (const float*)d_in[0];
    const void*  ei  = d_in[1];
    const float* W1  = (const float*)d_in[2];
    const float* as1 = (const float*)d_in[3];
    const float* ad1 = (const float*)d_in[4];
    const float* b1  = (const float*)d_in[5];
    const float* W2  = (const float*)d_in[6];
    const float* as2 = (const float*)d_in[7];
    const float* ad2 = (const float*)d_in[8];
    const float* b2  = (const float*)d_in[9];

    int E = in_sizes[1] / 2;
    int HC1 = in_sizes[5];          // 256
    int HC2 = in_sizes[9];          // 160
    int F = in_sizes[2] / HC1;      // 128
    int N = in_sizes[0] / F;        // 50000
    int C1 = HC1 / 4;               // 64
    int C2 = HC2 / 4;               // 40
    int nW1 = in_sizes[2];
    int nW2 = in_sizes[6];

    // fork point for the independent CSR chain
    cudaEventRecord(g_sc.e_fork, 0);

    // ---- main chain (legacy stream): stats -> fin16 -> gemm1 ----
    int nb = 400;
    int rowsPer = ceil_div(N, nb);
    colstats1<<<nb, FIN>>>(x, N, rowsPer);                          // launch 0
    colstats2<<<1, 512>>>(N, nb);                                   // launch 1
    {
        int work = N * (FIN / 8) + 4 * MAXN + nW1 + nW2;
        fin16_kernel<<<ceil_div(work, 256), 256>>>(x, W1, W2, N, nW1, nW2); // 2
    }
    {
        dim3 grid(ceil_div(N, 128), ceil_div(HC1, 64));
        gemm_f16_kernel<128, 256, 64, 0><<<grid, 256>>>(as1, ad1, N);       // 3
    }

    // ---- side chain: edge detect + CSR build (independent of main chain) ----
    cudaStreamWaitEvent(g_sc.side, g_sc.e_fork, 0);
    prep_kernel<<<ceil_div(N, 256) + 1, 256, 0, g_sc.side>>>(
        (const unsigned int*)ei, E, N);
    csr_count<<<ceil_div(E, 256), 256, 0, g_sc.side>>>(ei, E);
    csr_scan<<<1, 1024, 0, g_sc.side>>>(N);
    csr_scatter<<<ceil_div(E + N, 256), 256, 0, g_sc.side>>>(ei, E, N);
    cudaEventRecord(g_sc.e_join, g_sc.side);

    // join: agg1 needs both gemm1 (legacy) and CSR (side)
    cudaStreamWaitEvent(0, g_sc.e_join, 0);

    // ---- layer 1 aggregation ----
    agg_kernel<<<ceil_div(N, 8), 256>>>(b1, nullptr, 0, N, HC1, C1, 1, 0);

    // ---- layer 2 ----
    {
        dim3 grid(ceil_div(N, 128), ceil_div(HC2, 64));
        gemm_f16_kernel<256, 160, 40, 1><<<grid, 256>>>(as2, ad2, N);
    }
    agg_kernel<<<ceil_div(N, 8), 256>>>(b2, (float*)d_out, 1, N, HC2, C2, 0, 1);
}